// round 1
// baseline (speedup 1.0000x reference)
#include <cuda_runtime.h>
#include <math.h>

// ---------------- problem constants ----------------
#define NU   2048      // N_UTTS
#define SL   50        // SEQ_LEN
#define DE   300       // D_EMB
#define DF   64        // D_FILT
#define DOUT 100       // D_OUT
#define NC   7         // N_CLASSES
#define WIND 10
#define HOPS 3
#define NB   2047      // N_UTTS-1 (attention batch)
#define MTOT (NU*SL)   // 102400 token positions
#define NCOL 768       // 3*64 + 4*64 + 5*64 packed conv columns
#define FCAT 192       // 3*64 concat feature dim

// ---------------- scratch (static device memory; no allocs) ----------------
__device__ float g_Wall[DE*NCOL];                    // packed conv weights [K=300][C=768]
__device__ float g_Z[(size_t)MTOT*NCOL];             // per-position projections (315 MB)
__device__ float g_f[NU*FCAT];                       // pooled conv features
__device__ float g_sutt[NU*DOUT];                    // utterance encodings
__device__ float g_h[NB*DOUT];                       // GRU hidden state
__device__ float g_memb[NB*WIND*DOUT];               // memory bank
__device__ float g_q[NB*DOUT];                       // attention query accumulator
__device__ float g_attn_scratch[HOPS*NB*WIND];       // fallback attn sink

// ---------------- pack conv weights into Wall[k][c] ----------------
// column layout: c = off_fs + dt*64 + o ; off: fs3->0, fs4->192, fs5->448
__global__ void pack_wall(const float* __restrict__ w3,
                          const float* __restrict__ w4,
                          const float* __restrict__ w5) {
    int idx = blockIdx.x * blockDim.x + threadIdx.x;
    if (idx >= DE*NCOL) return;
    int k = idx / NCOL, c = idx % NCOL;
    float v;
    if (c < 192)      { int cc = c;       int dt = cc >> 6, o = cc & 63; v = w3[(o*3 + dt)*DE + k]; }
    else if (c < 448) { int cc = c - 192; int dt = cc >> 6, o = cc & 63; v = w4[(o*4 + dt)*DE + k]; }
    else              { int cc = c - 448; int dt = cc >> 6, o = cc & 63; v = w5[(o*5 + dt)*DE + k]; }
    g_Wall[idx] = v;
}

// ---------------- fused gather + SGEMM:  Z = emb[sents] @ Wall ----------------
// M=102400, K=300, N=768. BM=128 BN=64 BK=12 (300 = 25*12, no K guards), 256 thr,
// each thread computes 8x4 outputs.
#define BM 128
#define BN 64
#define BK 12
#define TM 8
#define TN 4
__global__ void __launch_bounds__(256) conv_gemm(const int* __restrict__ sents,
                                                 const float* __restrict__ emb) {
    __shared__ float As[BK][BM];
    __shared__ float Bs[BK][BN];
    __shared__ int   toks[BM];
    const int tid = threadIdx.x;
    const int bm = blockIdx.y, bn = blockIdx.x;

    if (tid < BM) toks[tid] = sents[bm*BM + tid];
    __syncthreads();

    const int ty = tid >> 4;        // 0..15 -> M
    const int tx = tid & 15;        // 0..15 -> N
    const int m_a  = tid >> 1;      // row this thread loads
    const int ks_a = (tid & 1) * 6; // k sub-segment (6 each)
    const float* arow = emb + (size_t)toks[m_a]*DE + ks_a;

    float acc[TM][TN];
    #pragma unroll
    for (int i = 0; i < TM; i++)
        #pragma unroll
        for (int j = 0; j < TN; j++) acc[i][j] = 0.f;

    for (int k0 = 0; k0 < DE; k0 += BK) {
        #pragma unroll
        for (int i = 0; i < 6; i++) As[ks_a + i][m_a] = arow[k0 + i];
        #pragma unroll
        for (int e = tid; e < BK*BN; e += 256) {
            int k = e >> 6, c = e & 63;
            Bs[k][c] = g_Wall[(k0 + k)*NCOL + bn*BN + c];
        }
        __syncthreads();
        #pragma unroll
        for (int k = 0; k < BK; k++) {
            float a[TM], b[TN];
            #pragma unroll
            for (int i = 0; i < TM; i++) a[i] = As[k][ty*TM + i];
            #pragma unroll
            for (int j = 0; j < TN; j++) b[j] = Bs[k][tx*TN + j];
            #pragma unroll
            for (int i = 0; i < TM; i++)
                #pragma unroll
                for (int j = 0; j < TN; j++) acc[i][j] += a[i]*b[j];
        }
        __syncthreads();
    }
    #pragma unroll
    for (int i = 0; i < TM; i++) {
        float4 v = make_float4(acc[i][0], acc[i][1], acc[i][2], acc[i][3]);
        *reinterpret_cast<float4*>(
            &g_Z[(size_t)(bm*BM + ty*TM + i)*NCOL + bn*BN + tx*TN]) = v;
    }
}

// ---------------- conv combine + relu + max-pool over time ----------------
__global__ void pool_kernel(const float* __restrict__ b3,
                            const float* __restrict__ b4,
                            const float* __restrict__ b5) {
    int id = blockIdx.x * blockDim.x + threadIdx.x;
    if (id >= NU*FCAT) return;
    int n = id / FCAT, fo = id % FCAT;
    int fi = fo >> 6, o = fo & 63;
    int fs  = 3 + fi;
    int off = (fi == 0) ? 0 : (fi == 1) ? 192 : 448;
    float bias = (fi == 0) ? b3[o] : (fi == 1) ? b4[o] : b5[o];
    int T = SL - fs + 1;
    float mx = -1e30f;
    for (int t = 0; t < T; t++) {
        float v = 0.f;
        #pragma unroll 5
        for (int dt = 0; dt < fs; dt++)
            v += g_Z[(size_t)(n*SL + t + dt)*NCOL + off + dt*64 + o];
        mx = fmaxf(mx, v);
    }
    g_f[id] = fmaxf(0.f, mx + bias);   // relu commutes with max (+const bias)
}

// ---------------- s_utt = tanh(f @ trans_w^T + trans_b) ----------------
__global__ void sutt_kernel(const float* __restrict__ tw,
                            const float* __restrict__ tb) {
    int id = blockIdx.x * blockDim.x + threadIdx.x;
    if (id >= NU*DOUT) return;
    int n = id / DOUT, d = id % DOUT;
    const float* fr = g_f + n*FCAT;
    const float* wr = tw + d*FCAT;
    float acc = tb[d];
    #pragma unroll 4
    for (int j = 0; j < FCAT; j++) acc += fr[j] * wr[j];
    g_sutt[id] = tanhf(acc);
}

// ---------------- one GRU step (8 batch rows / block) ----------------
// x[b] = (b+s-9 >= 0) ? s_utt[b+s-9] : 0 ;  h from g_h (zero at s==0)
// writes h_new to g_h and mem_bank[b][s] = x + h_new
__global__ void __launch_bounds__(256) gru_step(int s,
        const float* __restrict__ wih, const float* __restrict__ whh,
        const float* __restrict__ bih, const float* __restrict__ bhh) {
    __shared__ float xs[8][DOUT];
    __shared__ float hs[8][DOUT];
    __shared__ float gi[8][3*DOUT];
    __shared__ float gh[8][3*DOUT];
    const int tid = threadIdx.x;
    const int b0 = blockIdx.x * 8;

    for (int idx = tid; idx < 8*DOUT; idx += 256) {
        int r = idx / DOUT, d = idx % DOUT;
        int b = b0 + r;
        float xv = 0.f, hv = 0.f;
        if (b < NB) {
            int src = b + s - (WIND - 1);
            if (src >= 0) xv = g_sutt[src*DOUT + d];
            if (s > 0)    hv = g_h[b*DOUT + d];
        }
        xs[r][d] = xv; hs[r][d] = hv;
    }
    __syncthreads();

    for (int idx = tid; idx < 8*3*DOUT; idx += 256) {
        int r = idx / (3*DOUT), j = idx % (3*DOUT);
        const float4* wI = reinterpret_cast<const float4*>(wih + j*DOUT);
        const float4* wH = reinterpret_cast<const float4*>(whh + j*DOUT);
        const float4* xv = reinterpret_cast<const float4*>(xs[r]);
        const float4* hv = reinterpret_cast<const float4*>(hs[r]);
        float aI = 0.f, aH = 0.f;
        #pragma unroll
        for (int k = 0; k < DOUT/4; k++) {
            float4 wi = wI[k], wh = wH[k], x = xv[k], h = hv[k];
            aI += wi.x*x.x + wi.y*x.y + wi.z*x.z + wi.w*x.w;
            aH += wh.x*h.x + wh.y*h.y + wh.z*h.z + wh.w*h.w;
        }
        gi[r][j] = aI + bih[j];
        gh[r][j] = aH + bhh[j];
    }
    __syncthreads();

    for (int idx = tid; idx < 8*DOUT; idx += 256) {
        int r = idx / DOUT, d = idx % DOUT;
        int b = b0 + r;
        if (b >= NB) continue;
        float ir = gi[r][d],        hr = gh[r][d];
        float iz = gi[r][DOUT+d],   hz = gh[r][DOUT+d];
        float in = gi[r][2*DOUT+d], hn = gh[r][2*DOUT+d];
        float rr = 1.f / (1.f + expf(-(ir + hr)));
        float zz = 1.f / (1.f + expf(-(iz + hz)));
        float nn = tanhf(in + rr*hn);
        float hnew = (1.f - zz)*nn + zz*hs[r][d];
        g_h[b*DOUT + d] = hnew;
        g_memb[(b*WIND + s)*DOUT + d] = xs[r][d] + hnew;
    }
}

// ---------------- 3-hop attention; one block per window b ----------------
__global__ void attn_kernel(float* __restrict__ attn_out) {
    __shared__ float M[WIND][DOUT];
    __shared__ float q[DOUT];
    __shared__ float l[WIND];
    __shared__ float a[WIND];
    const int b = blockIdx.x;
    const int tid = threadIdx.x;

    for (int idx = tid; idx < WIND*DOUT; idx += blockDim.x)
        M[idx/DOUT][idx%DOUT] = g_memb[(b*WIND)*DOUT + idx];
    if (tid < DOUT) q[tid] = g_sutt[(b+1)*DOUT + tid];
    __syncthreads();

    for (int hop = 0; hop < HOPS; hop++) {
        if (tid < WIND) {
            float acc = 0.f;
            #pragma unroll 4
            for (int d = 0; d < DOUT; d++) acc += q[d] * M[tid][d];
            bool valid = (b + tid - (WIND - 1)) >= 0;
            l[tid] = valid ? acc : -1e10f;
        }
        __syncthreads();
        if (tid == 0) {
            float mx = -1e30f;
            for (int k = 0; k < WIND; k++) mx = fmaxf(mx, l[k]);
            float sum = 0.f;
            for (int k = 0; k < WIND; k++) { a[k] = expf(l[k] - mx); sum += a[k]; }
            float inv = 1.f / sum;
            for (int k = 0; k < WIND; k++) a[k] *= inv;
        }
        __syncthreads();
        if (tid < WIND)
            attn_out[hop*(NB*WIND) + b*WIND + tid] = a[tid];
        if (tid < DOUT) {
            float acc = 0.f;
            #pragma unroll
            for (int k = 0; k < WIND; k++) acc += a[k] * M[k][tid];
            q[tid] += acc;
        }
        __syncthreads();
    }
    if (tid < DOUT) g_q[b*DOUT + tid] = q[tid];
}

// ---------------- classifier + log_softmax ----------------
__global__ void cls_kernel(const float* __restrict__ cw,
                           const float* __restrict__ cb,
                           float* __restrict__ pred_out) {
    int row = blockIdx.x * blockDim.x + threadIdx.x;
    if (row >= NU) return;
    const float* s = (row == 0) ? g_sutt : (g_q + (row - 1)*DOUT);
    float lg[NC];
    #pragma unroll
    for (int c = 0; c < NC; c++) {
        float acc = cb[c];
        const float* wr = cw + c*DOUT;
        #pragma unroll 4
        for (int k = 0; k < DOUT; k++) acc += s[k] * wr[k];
        lg[c] = acc;
    }
    float mx = lg[0];
    #pragma unroll
    for (int c = 1; c < NC; c++) mx = fmaxf(mx, lg[c]);
    float sum = 0.f;
    #pragma unroll
    for (int c = 0; c < NC; c++) sum += expf(lg[c] - mx);
    float lse = mx + logf(sum);
    #pragma unroll
    for (int c = 0; c < NC; c++) pred_out[row*NC + c] = lg[c] - lse;
}

// ---------------- launch sequence ----------------
extern "C" void kernel_launch(void* const* d_in, const int* in_sizes, int n_in,
                              void* d_out, int out_size) {
    const int*   sents   = (const int*)  d_in[0];
    // d_in[1] = lengths (unused by reference)
    const float* emb     = (const float*)d_in[2];
    const float* trans_w = (const float*)d_in[3];
    const float* trans_b = (const float*)d_in[4];
    const float* gru_wih = (const float*)d_in[5];
    const float* gru_whh = (const float*)d_in[6];
    const float* gru_bih = (const float*)d_in[7];
    const float* gru_bhh = (const float*)d_in[8];
    const float* cls_w   = (const float*)d_in[9];
    const float* cls_b   = (const float*)d_in[10];
    const float* conv_w3 = (const float*)d_in[11];
    const float* conv_b3 = (const float*)d_in[12];
    const float* conv_w4 = (const float*)d_in[13];
    const float* conv_b4 = (const float*)d_in[14];
    const float* conv_w5 = (const float*)d_in[15];
    const float* conv_b5 = (const float*)d_in[16];

    float* outF = (float*)d_out;
    float* pred_out = outF;                               // 2048*7
    float* attn_out;
    if (out_size >= NU*NC + HOPS*NB*WIND) attn_out = outF + NU*NC;
    else { // unexpected layout: keep attn in scratch so pred is still right
        cudaGetSymbolAddress((void**)&attn_out, g_attn_scratch);
    }

    pack_wall<<<(DE*NCOL + 255)/256, 256>>>(conv_w3, conv_w4, conv_w5);

    dim3 ggrid(NCOL/BN, MTOT/BM);       // (12, 800)
    conv_gemm<<<ggrid, 256>>>(sents, emb);

    pool_kernel<<<(NU*FCAT + 255)/256, 256>>>(conv_b3, conv_b4, conv_b5);
    sutt_kernel<<<(NU*DOUT + 255)/256, 256>>>(trans_w, trans_b);

    for (int s = 0; s < WIND; s++)
        gru_step<<<(NB + 7)/8, 256>>>(s, gru_wih, gru_whh, gru_bih, gru_bhh);

    attn_kernel<<<NB, 128>>>(attn_out);
    cls_kernel<<<(NU + 255)/256, 256>>>(cls_w, cls_b, pred_out);
}

// round 2
// speedup vs baseline: 1.9862x; 1.9862x over previous
#include <cuda_runtime.h>
#include <math.h>

// ---------------- problem constants ----------------
#define NU    2048      // N_UTTS
#define SL    50        // SEQ_LEN
#define DE    300       // D_EMB
#define DOUT  100       // D_OUT
#define NC    7         // N_CLASSES
#define WIND  10
#define HOPS  3
#define NB    2047      // N_UTTS-1
#define VOCAB 50000
#define VPAD  50048     // 391 * 128  (GEMM M padding)
#define NCOL  768       // 3*64 + 4*64 + 5*64 packed conv columns
#define FCAT  192       // concat feature dim

// ---------------- static scratch ----------------
__device__ float g_Wall[DE*NCOL];                 // packed conv weights [K=300][C=768]
__device__ float g_Z[(size_t)VPAD*NCOL];          // per-VOCAB-row projections (154 MB)
__device__ float g_twT[FCAT*DOUT];                // trans_w transposed [192][100]
__device__ float g_sutt[NU*DOUT];                 // utterance encodings
__device__ float g_xproj[NB*3*DOUT];              // precomputed GRU input gates (incl bih)
__device__ float g_h[NB*DOUT];                    // GRU hidden state
__device__ float g_memb[NB*WIND*DOUT];            // memory bank
__device__ float g_q[NB*DOUT];                    // attention query accumulator
__device__ float g_attn_scratch[HOPS*NB*WIND];    // fallback attn sink

// ---------------- pack conv weights ----------------
__global__ void pack_wall(const float* __restrict__ w3,
                          const float* __restrict__ w4,
                          const float* __restrict__ w5) {
    int idx = blockIdx.x * blockDim.x + threadIdx.x;
    if (idx >= DE*NCOL) return;
    int k = idx / NCOL, c = idx % NCOL;
    float v;
    if (c < 192)      { int cc = c;       int dt = cc >> 6, o = cc & 63; v = w3[(o*3 + dt)*DE + k]; }
    else if (c < 448) { int cc = c - 192; int dt = cc >> 6, o = cc & 63; v = w4[(o*4 + dt)*DE + k]; }
    else              { int cc = c - 448; int dt = cc >> 6, o = cc & 63; v = w5[(o*5 + dt)*DE + k]; }
    g_Wall[idx] = v;
}

// ---------------- transpose trans_w -> [j][d] ----------------
__global__ void transpose_tw(const float* __restrict__ tw) {
    int idx = blockIdx.x * blockDim.x + threadIdx.x;
    if (idx >= FCAT*DOUT) return;
    int j = idx / DOUT, d = idx % DOUT;
    g_twT[idx] = tw[d*FCAT + j];
}

// ---------------- vocab-space SGEMM: Z = emb @ Wall ----------------
// M=50048, K=300, N=768. BM=128 BN=64 BK=12, 256 thr, 8x4 per thread.
#define BM 128
#define BN 64
#define BK 12
#define TM 8
#define TN 4
__global__ void __launch_bounds__(256) conv_gemm(const float* __restrict__ emb) {
    __shared__ float As[BK][BM];
    __shared__ float Bs[BK][BN];
    const int tid = threadIdx.x;
    const int bm = blockIdx.y, bn = blockIdx.x;

    const int ty = tid >> 4;
    const int tx = tid & 15;
    const int m_a  = tid >> 1;
    const int ks_a = (tid & 1) * 6;
    int row = bm*BM + m_a;
    if (row >= VOCAB) row = VOCAB - 1;   // padded rows: in-bounds junk
    const float* arow = emb + (size_t)row*DE + ks_a;

    float acc[TM][TN];
    #pragma unroll
    for (int i = 0; i < TM; i++)
        #pragma unroll
        for (int j = 0; j < TN; j++) acc[i][j] = 0.f;

    for (int k0 = 0; k0 < DE; k0 += BK) {
        #pragma unroll
        for (int i = 0; i < 6; i++) As[ks_a + i][m_a] = arow[k0 + i];
        #pragma unroll
        for (int e = tid; e < BK*BN; e += 256) {
            int k = e >> 6, c = e & 63;
            Bs[k][c] = g_Wall[(k0 + k)*NCOL + bn*BN + c];
        }
        __syncthreads();
        #pragma unroll
        for (int k = 0; k < BK; k++) {
            float a[TM], b[TN];
            #pragma unroll
            for (int i = 0; i < TM; i++) a[i] = As[k][ty*TM + i];
            #pragma unroll
            for (int j = 0; j < TN; j++) b[j] = Bs[k][tx*TN + j];
            #pragma unroll
            for (int i = 0; i < TM; i++)
                #pragma unroll
                for (int j = 0; j < TN; j++) acc[i][j] += a[i]*b[j];
        }
        __syncthreads();
    }
    #pragma unroll
    for (int i = 0; i < TM; i++) {
        float4 v = make_float4(acc[i][0], acc[i][1], acc[i][2], acc[i][3]);
        *reinterpret_cast<float4*>(
            &g_Z[(size_t)(bm*BM + ty*TM + i)*NCOL + bn*BN + tx*TN]) = v;
    }
}

// ---------------- fused pool + relu + tanh projection; 1 block / utterance ----
__global__ void __launch_bounds__(192) poolsutt_kernel(
        const int* __restrict__ sents,
        const float* __restrict__ b3, const float* __restrict__ b4,
        const float* __restrict__ b5, const float* __restrict__ tb) {
    __shared__ int   toks[SL];
    __shared__ float fsh[FCAT];
    const int n = blockIdx.x;
    const int tid = threadIdx.x;

    if (tid < SL) toks[tid] = sents[n*SL + tid];
    __syncthreads();

    // each thread: one concat-feature (fi, o)
    {
        int fi = tid >> 6, o = tid & 63;
        int fs  = 3 + fi;
        int off = (fi == 0) ? 0 : (fi == 1) ? 192 : 448;
        float bias = (fi == 0) ? b3[o] : (fi == 1) ? b4[o] : b5[o];
        int T = SL - fs + 1;
        float mx = -1e30f;
        for (int t = 0; t < T; t++) {
            float v = 0.f;
            #pragma unroll 5
            for (int dt = 0; dt < fs; dt++)
                v += g_Z[(size_t)toks[t + dt]*NCOL + off + dt*64 + o];
            mx = fmaxf(mx, v);
        }
        fsh[tid] = fmaxf(0.f, mx + bias);
    }
    __syncthreads();

    if (tid < DOUT) {
        float acc = tb[tid];
        #pragma unroll 8
        for (int j = 0; j < FCAT; j++) acc += fsh[j] * g_twT[j*DOUT + tid];
        g_sutt[n*DOUT + tid] = tanhf(acc);
    }
}

// ---------------- GRU input projection: xproj[v] = s_utt[v] @ wih^T + bih ----
__global__ void __launch_bounds__(256) xproj_kernel(
        const float* __restrict__ wih, const float* __restrict__ bih) {
    __shared__ float ss[16][DOUT];
    const int tid = threadIdx.x;
    const int v0 = blockIdx.x * 16;

    for (int idx = tid; idx < 16*DOUT; idx += 256) {
        int r = idx / DOUT, d = idx % DOUT;
        int v = v0 + r;
        ss[r][d] = (v < NB) ? g_sutt[v*DOUT + d] : 0.f;
    }
    __syncthreads();

    for (int idx = tid; idx < 16*3*DOUT; idx += 256) {
        int j = idx >> 4, r = idx & 15;       // consecutive threads share weight row
        int v = v0 + r;
        if (v >= NB) continue;
        const float4* wI = reinterpret_cast<const float4*>(wih + j*DOUT);
        const float4* xv = reinterpret_cast<const float4*>(ss[r]);
        float acc = 0.f;
        #pragma unroll
        for (int k = 0; k < DOUT/4; k++) {
            float4 w = wI[k], x = xv[k];
            acc += w.x*x.x + w.y*x.y + w.z*x.z + w.w*x.w;
        }
        g_xproj[v*3*DOUT + j] = acc + bih[j];
    }
}

// ---------------- one GRU step (16 batch rows / block) ----------------
__global__ void __launch_bounds__(256) gru_step(int s,
        const float* __restrict__ whh, const float* __restrict__ bhh,
        const float* __restrict__ bih) {
    __shared__ float hs[16][DOUT];
    __shared__ float gh[16][3*DOUT];
    const int tid = threadIdx.x;
    const int b0 = blockIdx.x * 16;

    for (int idx = tid; idx < 16*DOUT; idx += 256) {
        int r = idx / DOUT, d = idx % DOUT;
        int b = b0 + r;
        hs[r][d] = (b < NB && s > 0) ? g_h[b*DOUT + d] : 0.f;
    }
    __syncthreads();

    for (int idx = tid; idx < 16*3*DOUT; idx += 256) {
        int j = idx >> 4, r = idx & 15;
        const float4* wH = reinterpret_cast<const float4*>(whh + j*DOUT);
        const float4* hv = reinterpret_cast<const float4*>(hs[r]);
        float acc = 0.f;
        #pragma unroll
        for (int k = 0; k < DOUT/4; k++) {
            float4 w = wH[k], h = hv[k];
            acc += w.x*h.x + w.y*h.y + w.z*h.z + w.w*h.w;
        }
        gh[r][j] = acc + bhh[j];
    }
    __syncthreads();

    for (int idx = tid; idx < 16*DOUT; idx += 256) {
        int r = idx / DOUT, d = idx % DOUT;
        int b = b0 + r;
        if (b >= NB) continue;
        int src = b + s - (WIND - 1);
        float giR, giZ, giN, xv;
        if (src >= 0) {
            const float* xp = g_xproj + src*3*DOUT;
            giR = xp[d]; giZ = xp[DOUT + d]; giN = xp[2*DOUT + d];
            xv = g_sutt[src*DOUT + d];
        } else {
            giR = bih[d]; giZ = bih[DOUT + d]; giN = bih[2*DOUT + d];
            xv = 0.f;
        }
        float hr = gh[r][d], hz = gh[r][DOUT + d], hn = gh[r][2*DOUT + d];
        float rr = 1.f / (1.f + expf(-(giR + hr)));
        float zz = 1.f / (1.f + expf(-(giZ + hz)));
        float nn = tanhf(giN + rr*hn);
        float hnew = (1.f - zz)*nn + zz*hs[r][d];
        g_h[b*DOUT + d] = hnew;
        g_memb[(b*WIND + s)*DOUT + d] = xv + hnew;
    }
}

// ---------------- 3-hop attention; one block per window b ----------------
__global__ void attn_kernel(float* __restrict__ attn_out) {
    __shared__ float M[WIND][DOUT];
    __shared__ float q[DOUT];
    __shared__ float l[WIND];
    __shared__ float a[WIND];
    const int b = blockIdx.x;
    const int tid = threadIdx.x;

    for (int idx = tid; idx < WIND*DOUT; idx += blockDim.x)
        M[idx/DOUT][idx%DOUT] = g_memb[(b*WIND)*DOUT + idx];
    if (tid < DOUT) q[tid] = g_sutt[(b+1)*DOUT + tid];
    __syncthreads();

    for (int hop = 0; hop < HOPS; hop++) {
        if (tid < WIND) {
            float acc = 0.f;
            #pragma unroll 4
            for (int d = 0; d < DOUT; d++) acc += q[d] * M[tid][d];
            bool valid = (b + tid - (WIND - 1)) >= 0;
            l[tid] = valid ? acc : -1e10f;
        }
        __syncthreads();
        if (tid == 0) {
            float mx = -1e30f;
            for (int k = 0; k < WIND; k++) mx = fmaxf(mx, l[k]);
            float sum = 0.f;
            for (int k = 0; k < WIND; k++) { a[k] = expf(l[k] - mx); sum += a[k]; }
            float inv = 1.f / sum;
            for (int k = 0; k < WIND; k++) a[k] *= inv;
        }
        __syncthreads();
        if (tid < WIND)
            attn_out[hop*(NB*WIND) + b*WIND + tid] = a[tid];
        if (tid < DOUT) {
            float acc = 0.f;
            #pragma unroll
            for (int k = 0; k < WIND; k++) acc += a[k] * M[k][tid];
            q[tid] += acc;
        }
        __syncthreads();
    }
    if (tid < DOUT) g_q[b*DOUT + tid] = q[tid];
}

// ---------------- classifier + log_softmax ----------------
__global__ void cls_kernel(const float* __restrict__ cw,
                           const float* __restrict__ cb,
                           float* __restrict__ pred_out) {
    int row = blockIdx.x * blockDim.x + threadIdx.x;
    if (row >= NU) return;
    const float* s = (row == 0) ? g_sutt : (g_q + (row - 1)*DOUT);
    float lg[NC];
    #pragma unroll
    for (int c = 0; c < NC; c++) {
        float acc = cb[c];
        const float* wr = cw + c*DOUT;
        #pragma unroll 4
        for (int k = 0; k < DOUT; k++) acc += s[k] * wr[k];
        lg[c] = acc;
    }
    float mx = lg[0];
    #pragma unroll
    for (int c = 1; c < NC; c++) mx = fmaxf(mx, lg[c]);
    float sum = 0.f;
    #pragma unroll
    for (int c = 0; c < NC; c++) sum += expf(lg[c] - mx);
    float lse = mx + logf(sum);
    #pragma unroll
    for (int c = 0; c < NC; c++) pred_out[row*NC + c] = lg[c] - lse;
}

// ---------------- launch sequence ----------------
extern "C" void kernel_launch(void* const* d_in, const int* in_sizes, int n_in,
                              void* d_out, int out_size) {
    const int*   sents   = (const int*)  d_in[0];
    const float* emb     = (const float*)d_in[2];
    const float* trans_w = (const float*)d_in[3];
    const float* trans_b = (const float*)d_in[4];
    const float* gru_wih = (const float*)d_in[5];
    const float* gru_whh = (const float*)d_in[6];
    const float* gru_bih = (const float*)d_in[7];
    const float* gru_bhh = (const float*)d_in[8];
    const float* cls_w   = (const float*)d_in[9];
    const float* cls_b   = (const float*)d_in[10];
    const float* conv_w3 = (const float*)d_in[11];
    const float* conv_b3 = (const float*)d_in[12];
    const float* conv_w4 = (const float*)d_in[13];
    const float* conv_b4 = (const float*)d_in[14];
    const float* conv_w5 = (const float*)d_in[15];
    const float* conv_b5 = (const float*)d_in[16];

    float* outF = (float*)d_out;
    float* pred_out = outF;
    float* attn_out;
    if (out_size >= NU*NC + HOPS*NB*WIND) attn_out = outF + NU*NC;
    else cudaGetSymbolAddress((void**)&attn_out, g_attn_scratch);

    pack_wall<<<(DE*NCOL + 255)/256, 256>>>(conv_w3, conv_w4, conv_w5);
    transpose_tw<<<(FCAT*DOUT + 255)/256, 256>>>(trans_w);

    dim3 ggrid(NCOL/BN, VPAD/BM);   // (12, 391)
    conv_gemm<<<ggrid, 256>>>(emb);

    poolsutt_kernel<<<NU, 192>>>(sents, conv_b3, conv_b4, conv_b5, trans_b);
    xproj_kernel<<<(NB + 15)/16, 256>>>(gru_wih, gru_bih);

    for (int s = 0; s < WIND; s++)
        gru_step<<<(NB + 15)/16, 256>>>(s, gru_whh, gru_bhh, gru_bih);

    attn_kernel<<<NB, 128>>>(attn_out);
    cls_kernel<<<(NU + 255)/256, 256>>>(cls_w, cls_b, pred_out);
}

// round 4
// speedup vs baseline: 4.0911x; 2.0597x over previous
#include <cuda_runtime.h>
#include <math.h>
#include <stdint.h>

// ---------------- problem constants ----------------
#define NU    2048
#define SL    50
#define DE    300
#define KPAD  320      // DE padded to 10 chunks of 32
#define DOUT  100
#define NC    7
#define WIND  10
#define HOPS  3
#define NB    2047
#define VOCAB 50000
#define VPAD  50048    // 391 * 128
#define NCOL  768
#define FCAT  192

// ---------------- static scratch ----------------
__device__ float g_At[(size_t)VPAD*KPAD];        // tf32-rounded emb, K-padded
__device__ float g_WallT[NCOL*KPAD];             // tf32-rounded packed conv weights [c][k]
__device__ float g_Z[(size_t)VPAD*NCOL];         // per-vocab-row projections
__device__ float g_twT[FCAT*DOUT];
__device__ float g_sutt[NU*DOUT];
__device__ float g_xproj[NB*3*DOUT];
__device__ float g_memb[NB*WIND*DOUT];
__device__ float g_q[NB*DOUT];
__device__ float g_attn_scratch[HOPS*NB*WIND];

// ---------------- helpers ----------------
__device__ __forceinline__ uint32_t smem_u32(const void* p) {
    uint32_t a;
    asm("{ .reg .u64 t; cvta.to.shared.u64 t, %1; cvt.u32.u64 %0, t; }" : "=r"(a) : "l"(p));
    return a;
}
__device__ __forceinline__ float to_tf32(float x) {
    float r; asm("cvt.rna.tf32.f32 %0, %1;" : "=f"(r) : "f"(x)); return r;
}
#define CP_ASYNC16(sa, gp) asm volatile("cp.async.cg.shared.global [%0], [%1], 16;" :: "r"(sa), "l"(gp) : "memory")
#define CP_COMMIT()        asm volatile("cp.async.commit_group;" ::: "memory")
#define CP_WAIT(n)         asm volatile("cp.async.wait_group %0;" :: "n"(n) : "memory")

// m16n8k8 tf32 mma (sm_80+ family-stable; compiles for base sm_103)
__device__ __forceinline__ void mma_tf32(float* d, const uint32_t* a, const uint32_t* b) {
    asm volatile("mma.sync.aligned.m16n8k8.row.col.f32.tf32.tf32.f32 "
        "{%0,%1,%2,%3}, {%4,%5,%6,%7}, {%8,%9}, {%0,%1,%2,%3};"
        : "+f"(d[0]), "+f"(d[1]), "+f"(d[2]), "+f"(d[3])
        : "r"(a[0]), "r"(a[1]), "r"(a[2]), "r"(a[3]), "r"(b[0]), "r"(b[1]));
}

// ---------------- pack kernels ----------------
__global__ void pack_At(const float* __restrict__ emb) {
    size_t idx = (size_t)blockIdx.x * blockDim.x + threadIdx.x;
    if (idx >= (size_t)VPAD*KPAD) return;
    int row = (int)(idx / KPAD), k = (int)(idx % KPAD);
    float v = (row < VOCAB && k < DE) ? emb[(size_t)row*DE + k] : 0.f;
    g_At[idx] = to_tf32(v);
}
__global__ void pack_wallT(const float* __restrict__ w3,
                           const float* __restrict__ w4,
                           const float* __restrict__ w5) {
    int idx = blockIdx.x * blockDim.x + threadIdx.x;
    if (idx >= NCOL*KPAD) return;
    int c = idx / KPAD, k = idx % KPAD;
    float v = 0.f;
    if (k < DE) {
        if (c < 192)      { int cc = c;       int dt = cc >> 6, o = cc & 63; v = w3[(o*3 + dt)*DE + k]; }
        else if (c < 448) { int cc = c - 192; int dt = cc >> 6, o = cc & 63; v = w4[(o*4 + dt)*DE + k]; }
        else              { int cc = c - 448; int dt = cc >> 6, o = cc & 63; v = w5[(o*5 + dt)*DE + k]; }
    }
    g_WallT[idx] = to_tf32(v);
}
__global__ void transpose_tw(const float* __restrict__ tw) {
    int idx = blockIdx.x * blockDim.x + threadIdx.x;
    if (idx >= FCAT*DOUT) return;
    int j = idx / DOUT, d = idx % DOUT;
    g_twT[idx] = tw[d*FCAT + j];
}

// ---------------- tf32 mma GEMM: Z = At @ WallT^T ----------------
// CTA: 128x128 tile, 256 thr (8 warps, each 32x64), K = 10 chunks of 32,
// cp.async double-buffered smem, rows padded to 36 floats (16B align + bank spread).
#define LDK 36
#define CH_F (128*LDK)                 // floats per tile buffer
#define GEMM_SMEM (4*CH_F*4)           // A0,B0,A1,B1 = 73728 B

__global__ void __launch_bounds__(256, 2) conv_gemm_mma() {
    extern __shared__ float sm[];
    float* AS[2] = { sm,            sm + 2*CH_F };
    float* BS[2] = { sm + CH_F,     sm + 3*CH_F };
    const int tid  = threadIdx.x;
    const int lane = tid & 31, wid = tid >> 5;
    const int wm = (wid & 3) * 32;      // warp M offset in tile
    const int wn = (wid >> 2) * 64;     // warp N offset in tile
    const int m0 = blockIdx.y * 128;
    const int n0 = blockIdx.x * 128;

    const int sm_r  = tid >> 3;         // staging row (2 rows per 16 threads? -> 0..31 rows/iter)
    const int sm_c4 = tid & 7;          // float4 index within 32-float chunk
    uint32_t sA[2], sB[2];
    #pragma unroll
    for (int b = 0; b < 2; b++) { sA[b] = smem_u32(AS[b]); sB[b] = smem_u32(BS[b]); }

    float acc[2][8][4];
    #pragma unroll
    for (int mt = 0; mt < 2; mt++)
        #pragma unroll
        for (int nt = 0; nt < 8; nt++)
            #pragma unroll
            for (int i = 0; i < 4; i++) acc[mt][nt][i] = 0.f;

    // stage chunk 0
    #pragma unroll
    for (int i = 0; i < 4; i++) {
        int m = sm_r + i*32;
        CP_ASYNC16(sA[0] + (uint32_t)(m*LDK + sm_c4*4)*4, &g_At   [(size_t)(m0 + m)*KPAD + sm_c4*4]);
        CP_ASYNC16(sB[0] + (uint32_t)(m*LDK + sm_c4*4)*4, &g_WallT[(size_t)(n0 + m)*KPAD + sm_c4*4]);
    }
    CP_COMMIT();

    for (int c = 0; c < 10; c++) {
        const int buf = c & 1;
        if (c < 9) {
            const int nb = buf ^ 1, k0 = (c + 1) * 32;
            #pragma unroll
            for (int i = 0; i < 4; i++) {
                int m = sm_r + i*32;
                CP_ASYNC16(sA[nb] + (uint32_t)(m*LDK + sm_c4*4)*4, &g_At   [(size_t)(m0 + m)*KPAD + k0 + sm_c4*4]);
                CP_ASYNC16(sB[nb] + (uint32_t)(m*LDK + sm_c4*4)*4, &g_WallT[(size_t)(n0 + m)*KPAD + k0 + sm_c4*4]);
            }
            CP_COMMIT();
            CP_WAIT(1);
        } else {
            CP_WAIT(0);
        }
        __syncthreads();

        const float* As = AS[buf];
        const float* Bs = BS[buf];
        #pragma unroll
        for (int ks = 0; ks < 4; ks++) {
            const int k = ks * 8;
            uint32_t a[2][4], b[8][2];
            #pragma unroll
            for (int mt = 0; mt < 2; mt++) {
                int r0 = wm + mt*16 + (lane >> 2);
                int kc = k + (lane & 3);
                a[mt][0] = __float_as_uint(As[ r0      *LDK + kc    ]);
                a[mt][1] = __float_as_uint(As[(r0 + 8)*LDK + kc    ]);
                a[mt][2] = __float_as_uint(As[ r0      *LDK + kc + 4]);
                a[mt][3] = __float_as_uint(As[(r0 + 8)*LDK + kc + 4]);
            }
            #pragma unroll
            for (int nt = 0; nt < 8; nt++) {
                int c0 = wn + nt*8 + (lane >> 2);
                int kc = k + (lane & 3);
                b[nt][0] = __float_as_uint(Bs[c0*LDK + kc    ]);
                b[nt][1] = __float_as_uint(Bs[c0*LDK + kc + 4]);
            }
            #pragma unroll
            for (int mt = 0; mt < 2; mt++)
                #pragma unroll
                for (int nt = 0; nt < 8; nt++)
                    mma_tf32(acc[mt][nt], a[mt], b[nt]);
        }
        __syncthreads();
    }

    // epilogue: fragment -> g_Z (float2 stores)
    #pragma unroll
    for (int mt = 0; mt < 2; mt++) {
        int r = m0 + wm + mt*16 + (lane >> 2);
        #pragma unroll
        for (int nt = 0; nt < 8; nt++) {
            int cc = n0 + wn + nt*8 + (lane & 3)*2;
            *reinterpret_cast<float2*>(&g_Z[(size_t) r      *NCOL + cc]) =
                make_float2(acc[mt][nt][0], acc[mt][nt][1]);
            *reinterpret_cast<float2*>(&g_Z[(size_t)(r + 8)*NCOL + cc]) =
                make_float2(acc[mt][nt][2], acc[mt][nt][3]);
        }
    }
}

// ---------------- fused pool + relu + tanh projection ----------------
__global__ void __launch_bounds__(192) poolsutt_kernel(
        const int* __restrict__ sents,
        const float* __restrict__ b3, const float* __restrict__ b4,
        const float* __restrict__ b5, const float* __restrict__ tb) {
    __shared__ int   toks[SL];
    __shared__ float fsh[FCAT];
    const int n = blockIdx.x;
    const int tid = threadIdx.x;

    if (tid < SL) toks[tid] = sents[n*SL + tid];
    __syncthreads();
    {
        int fi = tid >> 6, o = tid & 63;
        int fs  = 3 + fi;
        int off = (fi == 0) ? 0 : (fi == 1) ? 192 : 448;
        float bias = (fi == 0) ? b3[o] : (fi == 1) ? b4[o] : b5[o];
        int T = SL - fs + 1;
        float mx = -1e30f;
        for (int t = 0; t < T; t++) {
            float v = 0.f;
            #pragma unroll 5
            for (int dt = 0; dt < fs; dt++)
                v += g_Z[(size_t)toks[t + dt]*NCOL + off + dt*64 + o];
            mx = fmaxf(mx, v);
        }
        fsh[tid] = fmaxf(0.f, mx + bias);
    }
    __syncthreads();
    if (tid < DOUT) {
        float acc = tb[tid];
        #pragma unroll 8
        for (int j = 0; j < FCAT; j++) acc += fsh[j] * g_twT[j*DOUT + tid];
        g_sutt[n*DOUT + tid] = tanhf(acc);
    }
}

// ---------------- GRU input projection ----------------
__global__ void __launch_bounds__(256) xproj_kernel(
        const float* __restrict__ wih, const float* __restrict__ bih) {
    __shared__ float ss[16][DOUT];
    const int tid = threadIdx.x;
    const int v0 = blockIdx.x * 16;
    for (int idx = tid; idx < 16*DOUT; idx += 256) {
        int r = idx / DOUT, d = idx % DOUT;
        int v = v0 + r;
        ss[r][d] = (v < NB) ? g_sutt[v*DOUT + d] : 0.f;
    }
    __syncthreads();
    for (int idx = tid; idx < 16*3*DOUT; idx += 256) {
        int j = idx >> 4, r = idx & 15;
        int v = v0 + r;
        if (v >= NB) continue;
        const float4* wI = reinterpret_cast<const float4*>(wih + j*DOUT);
        const float4* xv = reinterpret_cast<const float4*>(ss[r]);
        float acc = 0.f;
        #pragma unroll
        for (int k = 0; k < DOUT/4; k++) {
            float4 w = wI[k], x = xv[k];
            acc += w.x*x.x + w.y*x.y + w.z*x.z + w.w*x.w;
        }
        g_xproj[v*3*DOUT + j] = acc + bih[j];
    }
}

// ---------------- fused GRU: all 10 steps, whh resident in smem ----------------
#define GRU_SMEM ((30000 + 300 + 300 + 1600 + 4800) * 4)
__global__ void __launch_bounds__(256) gru_fused(
        const float* __restrict__ whh, const float* __restrict__ bhh,
        const float* __restrict__ bih) {
    extern __shared__ float smg[];
    float* whh_s = smg;
    float* bhh_s = smg + 30000;
    float* bih_s = bhh_s + 300;
    float* hs    = bih_s + 300;        // [16][100]
    float* gh    = hs + 1600;          // [16][300]
    const int tid = threadIdx.x;
    const int b0 = blockIdx.x * 16;

    for (int i = tid; i < 30000; i += 256) whh_s[i] = whh[i];
    for (int i = tid; i < 300; i += 256) { bhh_s[i] = bhh[i]; bih_s[i] = bih[i]; }
    for (int i = tid; i < 1600; i += 256) hs[i] = 0.f;
    __syncthreads();

    for (int s = 0; s < WIND; s++) {
        for (int idx = tid; idx < 16*3*DOUT; idx += 256) {
            int j = idx >> 4, r = idx & 15;
            const float4* wH = reinterpret_cast<const float4*>(whh_s + j*DOUT);
            const float4* hv = reinterpret_cast<const float4*>(hs + r*DOUT);
            float acc = 0.f;
            #pragma unroll
            for (int k = 0; k < DOUT/4; k++) {
                float4 w = wH[k], h = hv[k];
                acc += w.x*h.x + w.y*h.y + w.z*h.z + w.w*h.w;
            }
            gh[r*3*DOUT + j] = acc + bhh_s[j];
        }
        __syncthreads();
        for (int idx = tid; idx < 16*DOUT; idx += 256) {
            int r = idx / DOUT, d = idx % DOUT;
            int b = b0 + r;
            if (b >= NB) continue;
            int src = b + s - (WIND - 1);
            float giR, giZ, giN, xv;
            if (src >= 0) {
                const float* xp = g_xproj + src*3*DOUT;
                giR = xp[d]; giZ = xp[DOUT + d]; giN = xp[2*DOUT + d];
                xv = g_sutt[src*DOUT + d];
            } else {
                giR = bih_s[d]; giZ = bih_s[DOUT + d]; giN = bih_s[2*DOUT + d];
                xv = 0.f;
            }
            float hr = gh[r*3*DOUT + d], hz = gh[r*3*DOUT + DOUT + d], hn = gh[r*3*DOUT + 2*DOUT + d];
            float rr = 1.f / (1.f + expf(-(giR + hr)));
            float zz = 1.f / (1.f + expf(-(giZ + hz)));
            float nn = tanhf(giN + rr*hn);
            float hnew = (1.f - zz)*nn + zz*hs[r*DOUT + d];
            hs[r*DOUT + d] = hnew;
            g_memb[(b*WIND + s)*DOUT + d] = xv + hnew;
        }
        __syncthreads();
    }
}

// ---------------- 3-hop attention ----------------
__global__ void attn_kernel(float* __restrict__ attn_out) {
    __shared__ float M[WIND][DOUT];
    __shared__ float q[DOUT];
    __shared__ float l[WIND];
    __shared__ float a[WIND];
    const int b = blockIdx.x;
    const int tid = threadIdx.x;

    for (int idx = tid; idx < WIND*DOUT; idx += blockDim.x)
        M[idx/DOUT][idx%DOUT] = g_memb[(b*WIND)*DOUT + idx];
    if (tid < DOUT) q[tid] = g_sutt[(b+1)*DOUT + tid];
    __syncthreads();

    for (int hop = 0; hop < HOPS; hop++) {
        if (tid < WIND) {
            float acc = 0.f;
            #pragma unroll 4
            for (int d = 0; d < DOUT; d++) acc += q[d] * M[tid][d];
            bool valid = (b + tid - (WIND - 1)) >= 0;
            l[tid] = valid ? acc : -1e10f;
        }
        __syncthreads();
        if (tid == 0) {
            float mx = -1e30f;
            for (int k = 0; k < WIND; k++) mx = fmaxf(mx, l[k]);
            float sum = 0.f;
            for (int k = 0; k < WIND; k++) { a[k] = expf(l[k] - mx); sum += a[k]; }
            float inv = 1.f / sum;
            for (int k = 0; k < WIND; k++) a[k] *= inv;
        }
        __syncthreads();
        if (tid < WIND)
            attn_out[hop*(NB*WIND) + b*WIND + tid] = a[tid];
        if (tid < DOUT) {
            float acc = 0.f;
            #pragma unroll
            for (int k = 0; k < WIND; k++) acc += a[k] * M[k][tid];
            q[tid] += acc;
        }
        __syncthreads();
    }
    if (tid < DOUT) g_q[b*DOUT + tid] = q[tid];
}

// ---------------- classifier + log_softmax ----------------
__global__ void cls_kernel(const float* __restrict__ cw,
                           const float* __restrict__ cb,
                           float* __restrict__ pred_out) {
    int row = blockIdx.x * blockDim.x + threadIdx.x;
    if (row >= NU) return;
    const float* s = (row == 0) ? g_sutt : (g_q + (row - 1)*DOUT);
    float lg[NC];
    #pragma unroll
    for (int c = 0; c < NC; c++) {
        float acc = cb[c];
        const float* wr = cw + c*DOUT;
        #pragma unroll 4
        for (int k = 0; k < DOUT; k++) acc += s[k] * wr[k];
        lg[c] = acc;
    }
    float mx = lg[0];
    #pragma unroll
    for (int c = 1; c < NC; c++) mx = fmaxf(mx, lg[c]);
    float sum = 0.f;
    #pragma unroll
    for (int c = 0; c < NC; c++) sum += expf(lg[c] - mx);
    float lse = mx + logf(sum);
    #pragma unroll
    for (int c = 0; c < NC; c++) pred_out[row*NC + c] = lg[c] - lse;
}

// ---------------- launch sequence ----------------
extern "C" void kernel_launch(void* const* d_in, const int* in_sizes, int n_in,
                              void* d_out, int out_size) {
    const int*   sents   = (const int*)  d_in[0];
    const float* emb     = (const float*)d_in[2];
    const float* trans_w = (const float*)d_in[3];
    const float* trans_b = (const float*)d_in[4];
    const float* gru_wih = (const float*)d_in[5];
    const float* gru_whh = (const float*)d_in[6];
    const float* gru_bih = (const float*)d_in[7];
    const float* gru_bhh = (const float*)d_in[8];
    const float* cls_w   = (const float*)d_in[9];
    const float* cls_b   = (const float*)d_in[10];
    const float* conv_w3 = (const float*)d_in[11];
    const float* conv_b3 = (const float*)d_in[12];
    const float* conv_w4 = (const float*)d_in[13];
    const float* conv_b4 = (const float*)d_in[14];
    const float* conv_w5 = (const float*)d_in[15];
    const float* conv_b5 = (const float*)d_in[16];

    float* outF = (float*)d_out;
    float* pred_out = outF;
    float* attn_out;
    if (out_size >= NU*NC + HOPS*NB*WIND) attn_out = outF + NU*NC;
    else cudaGetSymbolAddress((void**)&attn_out, g_attn_scratch);

    cudaFuncSetAttribute(conv_gemm_mma, cudaFuncAttributeMaxDynamicSharedMemorySize, GEMM_SMEM);
    cudaFuncSetAttribute(gru_fused,     cudaFuncAttributeMaxDynamicSharedMemorySize, GRU_SMEM);

    pack_At<<<(int)(((size_t)VPAD*KPAD + 255)/256), 256>>>(emb);
    pack_wallT<<<(NCOL*KPAD + 255)/256, 256>>>(conv_w3, conv_w4, conv_w5);
    transpose_tw<<<(FCAT*DOUT + 255)/256, 256>>>(trans_w);

    dim3 ggrid(NCOL/128, VPAD/128);   // (6, 391)
    conv_gemm_mma<<<ggrid, 256, GEMM_SMEM>>>();

    poolsutt_kernel<<<NU, 192>>>(sents, conv_b3, conv_b4, conv_b5, trans_b);
    xproj_kernel<<<(NB + 15)/16, 256>>>(gru_wih, gru_bih);
    gru_fused<<<(NB + 15)/16, 256, GRU_SMEM>>>(gru_whh, gru_bhh, gru_bih);

    attn_kernel<<<NB, 128>>>(attn_out);
    cls_kernel<<<(NU + 255)/256, 256>>>(cls_w, cls_b, pred_out);
}

// round 5
// speedup vs baseline: 4.8205x; 1.1783x over previous
#include <cuda_runtime.h>
#include <math.h>
#include <stdint.h>

// ---------------- problem constants ----------------
#define NU    2048
#define SL    50
#define DE    300
#define KPAD  320      // 40 k-groups of 8; 10 chunks of 32
#define DOUT  100
#define NC    7
#define WIND  10
#define HOPS  3
#define NB    2047
#define VOCAB 50000
#define VPAD  50048    // 391 * 128
#define NCOL  768
#define FCAT  192

// ---------------- static scratch ----------------
// g_At: A in mma-fragment order: f4[((mblk*40 + kc8)*8 + r16)*32 + lane], regs 0..3 inside
__device__ float g_At[(size_t)VPAD*KPAD];
// g_WallT: B fragment order: f2[((nblk*40 + kc8)*32 + n8)*32 + lane], regs 0..1 inside
__device__ float g_WallT[NCOL*KPAD];
__device__ float g_Z[(size_t)VPAD*NCOL];
__device__ float g_twT[FCAT*DOUT];
__device__ float g_sutt[NU*DOUT];
__device__ float g_xproj[NB*3*DOUT];
__device__ float g_memb[NB*WIND*DOUT];
__device__ float g_q[NB*DOUT];
__device__ float g_attn_scratch[HOPS*NB*WIND];

// ---------------- helpers ----------------
__device__ __forceinline__ uint32_t smem_u32(const void* p) {
    uint32_t a;
    asm("{ .reg .u64 t; cvta.to.shared.u64 t, %1; cvt.u32.u64 %0, t; }" : "=r"(a) : "l"(p));
    return a;
}
__device__ __forceinline__ float to_tf32(float x) {
    float r; asm("cvt.rna.tf32.f32 %0, %1;" : "=f"(r) : "f"(x)); return r;
}
#define CP_ASYNC16(sa, gp) asm volatile("cp.async.cg.shared.global [%0], [%1], 16;" :: "r"(sa), "l"(gp) : "memory")
#define CP_COMMIT()        asm volatile("cp.async.commit_group;" ::: "memory")
#define CP_WAIT(n)         asm volatile("cp.async.wait_group %0;" :: "n"(n) : "memory")

__device__ __forceinline__ void mma_tf32(float* d, const uint32_t* a, const uint32_t* b) {
    asm volatile("mma.sync.aligned.m16n8k8.row.col.f32.tf32.tf32.f32 "
        "{%0,%1,%2,%3}, {%4,%5,%6,%7}, {%8,%9}, {%0,%1,%2,%3};"
        : "+f"(d[0]), "+f"(d[1]), "+f"(d[2]), "+f"(d[3])
        : "r"(a[0]), "r"(a[1]), "r"(a[2]), "r"(a[3]), "r"(b[0]), "r"(b[1]));
}

// ---------------- pack A (dst-linear, fragment order) ----------------
// float4 d4: lane=d4&31, r16=(d4>>5)&7, kc8=(d4>>8)%40, mblk=(d4>>8)/40
// regs: {A[m][k], A[m+8][k], A[m][k+4], A[m+8][k+4]}, m=mblk*128+r16*16+(lane>>2), k=kc8*8+(lane&3)
__device__ __forceinline__ float emb_at(const float* emb, int m, int k) {
    if (m >= VOCAB || k >= DE) return 0.f;
    return to_tf32(emb[(size_t)m*DE + k]);
}
__global__ void pack_At(const float* __restrict__ emb) {
    size_t d4 = (size_t)blockIdx.x * blockDim.x + threadIdx.x;
    if (d4 >= (size_t)VPAD*KPAD/4) return;
    int lane = (int)(d4 & 31);
    int r16  = (int)((d4 >> 5) & 7);
    size_t rest = d4 >> 8;
    int kc8  = (int)(rest % 40);
    int mblk = (int)(rest / 40);
    int m = mblk*128 + r16*16 + (lane >> 2);
    int k = kc8*8 + (lane & 3);
    float4 v = make_float4(emb_at(emb, m, k),     emb_at(emb, m + 8, k),
                           emb_at(emb, m, k + 4), emb_at(emb, m + 8, k + 4));
    reinterpret_cast<float4*>(g_At)[d4] = v;
}

// ---------------- pack B (dst-linear, fragment order) ----------------
__device__ __forceinline__ float wall_at(const float* w3, const float* w4,
                                         const float* w5, int c, int k) {
    if (k >= DE) return 0.f;
    float v;
    if (c < 192)      { int cc = c;       int dt = cc >> 6, o = cc & 63; v = w3[(o*3 + dt)*DE + k]; }
    else if (c < 448) { int cc = c - 192; int dt = cc >> 6, o = cc & 63; v = w4[(o*4 + dt)*DE + k]; }
    else              { int cc = c - 448; int dt = cc >> 6, o = cc & 63; v = w5[(o*5 + dt)*DE + k]; }
    return to_tf32(v);
}
__global__ void pack_wallT(const float* __restrict__ w3,
                           const float* __restrict__ w4,
                           const float* __restrict__ w5) {
    int d2 = blockIdx.x * blockDim.x + threadIdx.x;
    if (d2 >= NCOL*KPAD/2) return;
    int lane = d2 & 31;
    int n8   = (d2 >> 5) & 31;
    int rest = d2 >> 10;
    int kc8  = rest % 40;
    int nblk = rest / 40;
    int n = nblk*256 + n8*8 + (lane >> 2);
    int k = kc8*8 + (lane & 3);
    float2 v = make_float2(wall_at(w3, w4, w5, n, k), wall_at(w3, w4, w5, n, k + 4));
    reinterpret_cast<float2*>(g_WallT)[d2] = v;
}

__global__ void transpose_tw(const float* __restrict__ tw) {
    int idx = blockIdx.x * blockDim.x + threadIdx.x;
    if (idx >= FCAT*DOUT) return;
    int j = idx / DOUT, d = idx % DOUT;
    g_twT[idx] = tw[d*FCAT + j];
}

// ---------------- tf32 mma GEMM: Z = At @ WallT^T ----------------
// CTA 128(M) x 256(N), 512 thr = 16 warps (4x4), warp tile 32x64.
// K = 10 chunks of 32. Double-buffered contiguous cp.async staging.
// smem floats: A0[0,4096) A1[4096,8192) B0[8192,16384) B1[16384,24576)
#define GEMM_SMEM (24576*4)

__global__ void __launch_bounds__(512, 1) conv_gemm_mma() {
    extern __shared__ float sm[];
    const int tid  = threadIdx.x;
    const int lane = tid & 31, wid = tid >> 5;
    const int warp_m = wid & 3;          // 0..3 -> M offset warp_m*32
    const int warp_n = wid >> 2;         // 0..3 -> N offset warp_n*64
    const int by = blockIdx.y, bx = blockIdx.x;
    const int m0 = by * 128, n0 = bx * 256;

    const uint32_t smb = smem_u32(sm);
    const float4* At4 = reinterpret_cast<const float4*>(g_At);
    const float4* Bt4 = reinterpret_cast<const float4*>(g_WallT);

    float acc[2][8][4];
    #pragma unroll
    for (int mt = 0; mt < 2; mt++)
        #pragma unroll
        for (int nt = 0; nt < 8; nt++)
            #pragma unroll
            for (int i = 0; i < 4; i++) acc[mt][nt][i] = 0.f;

    // stage chunk 0
    {
        size_t aG = ((size_t)by*40 + 0) * 256;      // float4: 40 kc8 * 8 r16 * 32 / per kc8: 256
        size_t bG = ((size_t)bx*40 + 0) * 512;      // float4 per kc8: 1024 f2 = 512 f4
        #pragma unroll
        for (int i = 0; i < 2; i++)
            CP_ASYNC16(smb + (tid + i*512)*16, At4 + aG + tid + i*512);
        #pragma unroll
        for (int i = 0; i < 4; i++)
            CP_ASYNC16(smb + 32768 + (tid + i*512)*16, Bt4 + bG + tid + i*512);
        CP_COMMIT();
    }

    for (int c = 0; c < 10; c++) {
        const int buf = c & 1;
        if (c < 9) {
            const int nb = buf ^ 1;
            size_t aG = ((size_t)by*40 + (c + 1)*4) * 256;
            size_t bG = ((size_t)bx*40 + (c + 1)*4) * 512;
            #pragma unroll
            for (int i = 0; i < 2; i++)
                CP_ASYNC16(smb + nb*16384 + (tid + i*512)*16, At4 + aG + tid + i*512);
            #pragma unroll
            for (int i = 0; i < 4; i++)
                CP_ASYNC16(smb + 32768 + nb*32768 + (tid + i*512)*16, Bt4 + bG + tid + i*512);
            CP_COMMIT();
            CP_WAIT(1);
        } else {
            CP_WAIT(0);
        }
        __syncthreads();

        const float4* A4 = reinterpret_cast<const float4*>(sm + buf*4096);
        const float2* B2 = reinterpret_cast<const float2*>(sm + 8192 + buf*8192);
        #pragma unroll
        for (int ks = 0; ks < 4; ks++) {
            uint32_t a[2][4], b[8][2];
            #pragma unroll
            for (int mt = 0; mt < 2; mt++) {
                float4 v = A4[(ks*8 + warp_m*2 + mt)*32 + lane];
                a[mt][0] = __float_as_uint(v.x); a[mt][1] = __float_as_uint(v.y);
                a[mt][2] = __float_as_uint(v.z); a[mt][3] = __float_as_uint(v.w);
            }
            #pragma unroll
            for (int nt = 0; nt < 8; nt++) {
                float2 u = B2[(ks*32 + warp_n*8 + nt)*32 + lane];
                b[nt][0] = __float_as_uint(u.x); b[nt][1] = __float_as_uint(u.y);
            }
            #pragma unroll
            for (int mt = 0; mt < 2; mt++)
                #pragma unroll
                for (int nt = 0; nt < 8; nt++)
                    mma_tf32(acc[mt][nt], a[mt], b[nt]);
        }
        __syncthreads();
    }

    // epilogue
    #pragma unroll
    for (int mt = 0; mt < 2; mt++) {
        int r = m0 + warp_m*32 + mt*16 + (lane >> 2);
        #pragma unroll
        for (int nt = 0; nt < 8; nt++) {
            int cc = n0 + warp_n*64 + nt*8 + (lane & 3)*2;
            *reinterpret_cast<float2*>(&g_Z[(size_t) r      *NCOL + cc]) =
                make_float2(acc[mt][nt][0], acc[mt][nt][1]);
            *reinterpret_cast<float2*>(&g_Z[(size_t)(r + 8)*NCOL + cc]) =
                make_float2(acc[mt][nt][2], acc[mt][nt][3]);
        }
    }
}

// ---------------- fused pool + relu + tanh projection (2-way t-split) -------
__global__ void __launch_bounds__(384) poolsutt_kernel(
        const int* __restrict__ sents,
        const float* __restrict__ b3, const float* __restrict__ b4,
        const float* __restrict__ b5, const float* __restrict__ tb) {
    __shared__ int   toks[SL];
    __shared__ float pmax[384];
    __shared__ float fsh[FCAT];
    const int n = blockIdx.x;
    const int tid = threadIdx.x;

    if (tid < SL) toks[tid] = sents[n*SL + tid];
    __syncthreads();
    {
        const int half = tid / FCAT;           // 0 or 1
        const int f = tid - half*FCAT;
        const int fi = f >> 6, o = f & 63;
        const int fs  = 3 + fi;
        const int off = (fi == 0) ? 0 : (fi == 1) ? 192 : 448;
        const int T = SL - fs + 1;
        const int t0 = half ? (T >> 1) : 0;
        const int t1 = half ? T : (T >> 1);
        float mx = -1e30f;
        for (int t = t0; t < t1; t++) {
            float v = 0.f;
            #pragma unroll 5
            for (int dt = 0; dt < fs; dt++)
                v += g_Z[(size_t)toks[t + dt]*NCOL + off + dt*64 + o];
            mx = fmaxf(mx, v);
        }
        pmax[tid] = mx;
    }
    __syncthreads();
    if (tid < FCAT) {
        int fi = tid >> 6, o = tid & 63;
        float bias = (fi == 0) ? b3[o] : (fi == 1) ? b4[o] : b5[o];
        float mx = fmaxf(pmax[tid], pmax[tid + FCAT]);
        fsh[tid] = fmaxf(0.f, mx + bias);
    }
    __syncthreads();
    if (tid < DOUT) {
        float acc = tb[tid];
        #pragma unroll 8
        for (int j = 0; j < FCAT; j++) acc += fsh[j] * g_twT[j*DOUT + tid];
        g_sutt[n*DOUT + tid] = tanhf(acc);
    }
}

// ---------------- GRU input projection ----------------
__global__ void __launch_bounds__(256) xproj_kernel(
        const float* __restrict__ wih, const float* __restrict__ bih) {
    __shared__ float ss[16][DOUT];
    const int tid = threadIdx.x;
    const int v0 = blockIdx.x * 16;
    for (int idx = tid; idx < 16*DOUT; idx += 256) {
        int r = idx / DOUT, d = idx % DOUT;
        int v = v0 + r;
        ss[r][d] = (v < NB) ? g_sutt[v*DOUT + d] : 0.f;
    }
    __syncthreads();
    for (int idx = tid; idx < 16*3*DOUT; idx += 256) {
        int j = idx >> 4, r = idx & 15;
        int v = v0 + r;
        if (v >= NB) continue;
        const float4* wI = reinterpret_cast<const float4*>(wih + j*DOUT);
        const float4* xv = reinterpret_cast<const float4*>(ss[r]);
        float acc = 0.f;
        #pragma unroll
        for (int k = 0; k < DOUT/4; k++) {
            float4 w = wI[k], x = xv[k];
            acc += w.x*x.x + w.y*x.y + w.z*x.z + w.w*x.w;
        }
        g_xproj[v*3*DOUT + j] = acc + bih[j];
    }
}

// ---------------- fused GRU: all 10 steps, whh resident in smem ----------------
#define GRU_SMEM ((30000 + 300 + 300 + 1600 + 4800) * 4)
__global__ void __launch_bounds__(256) gru_fused(
        const float* __restrict__ whh, const float* __restrict__ bhh,
        const float* __restrict__ bih) {
    extern __shared__ float smg[];
    float* whh_s = smg;
    float* bhh_s = smg + 30000;
    float* bih_s = bhh_s + 300;
    float* hs    = bih_s + 300;        // [16][100]
    float* gh    = hs + 1600;          // [16][300]
    const int tid = threadIdx.x;
    const int b0 = blockIdx.x * 16;

    for (int i = tid; i < 30000; i += 256) whh_s[i] = whh[i];
    for (int i = tid; i < 300; i += 256) { bhh_s[i] = bhh[i]; bih_s[i] = bih[i]; }
    for (int i = tid; i < 1600; i += 256) hs[i] = 0.f;
    __syncthreads();

    for (int s = 0; s < WIND; s++) {
        for (int idx = tid; idx < 16*3*DOUT; idx += 256) {
            int j = idx >> 4, r = idx & 15;
            const float4* wH = reinterpret_cast<const float4*>(whh_s + j*DOUT);
            const float4* hv = reinterpret_cast<const float4*>(hs + r*DOUT);
            float acc = 0.f;
            #pragma unroll
            for (int k = 0; k < DOUT/4; k++) {
                float4 w = wH[k], h = hv[k];
                acc += w.x*h.x + w.y*h.y + w.z*h.z + w.w*h.w;
            }
            gh[r*3*DOUT + j] = acc + bhh_s[j];
        }
        __syncthreads();
        for (int idx = tid; idx < 16*DOUT; idx += 256) {
            int r = idx / DOUT, d = idx % DOUT;
            int b = b0 + r;
            if (b >= NB) continue;
            int src = b + s - (WIND - 1);
            float giR, giZ, giN, xv;
            if (src >= 0) {
                const float* xp = g_xproj + src*3*DOUT;
                giR = xp[d]; giZ = xp[DOUT + d]; giN = xp[2*DOUT + d];
                xv = g_sutt[src*DOUT + d];
            } else {
                giR = bih_s[d]; giZ = bih_s[DOUT + d]; giN = bih_s[2*DOUT + d];
                xv = 0.f;
            }
            float hr = gh[r*3*DOUT + d], hz = gh[r*3*DOUT + DOUT + d], hn = gh[r*3*DOUT + 2*DOUT + d];
            float rr = 1.f / (1.f + expf(-(giR + hr)));
            float zz = 1.f / (1.f + expf(-(giZ + hz)));
            float nn = tanhf(giN + rr*hn);
            float hnew = (1.f - zz)*nn + zz*hs[r*DOUT + d];
            hs[r*DOUT + d] = hnew;
            g_memb[(b*WIND + s)*DOUT + d] = xv + hnew;
        }
        __syncthreads();
    }
}

// ---------------- 3-hop attention ----------------
__global__ void attn_kernel(float* __restrict__ attn_out) {
    __shared__ float M[WIND][DOUT];
    __shared__ float q[DOUT];
    __shared__ float l[WIND];
    __shared__ float a[WIND];
    const int b = blockIdx.x;
    const int tid = threadIdx.x;

    for (int idx = tid; idx < WIND*DOUT; idx += blockDim.x)
        M[idx/DOUT][idx%DOUT] = g_memb[(b*WIND)*DOUT + idx];
    if (tid < DOUT) q[tid] = g_sutt[(b+1)*DOUT + tid];
    __syncthreads();

    for (int hop = 0; hop < HOPS; hop++) {
        if (tid < WIND) {
            float acc = 0.f;
            #pragma unroll 4
            for (int d = 0; d < DOUT; d++) acc += q[d] * M[tid][d];
            bool valid = (b + tid - (WIND - 1)) >= 0;
            l[tid] = valid ? acc : -1e10f;
        }
        __syncthreads();
        if (tid == 0) {
            float mx = -1e30f;
            for (int k = 0; k < WIND; k++) mx = fmaxf(mx, l[k]);
            float sum = 0.f;
            for (int k = 0; k < WIND; k++) { a[k] = expf(l[k] - mx); sum += a[k]; }
            float inv = 1.f / sum;
            for (int k = 0; k < WIND; k++) a[k] *= inv;
        }
        __syncthreads();
        if (tid < WIND)
            attn_out[hop*(NB*WIND) + b*WIND + tid] = a[tid];
        if (tid < DOUT) {
            float acc = 0.f;
            #pragma unroll
            for (int k = 0; k < WIND; k++) acc += a[k] * M[k][tid];
            q[tid] += acc;
        }
        __syncthreads();
    }
    if (tid < DOUT) g_q[b*DOUT + tid] = q[tid];
}

// ---------------- classifier + log_softmax ----------------
__global__ void cls_kernel(const float* __restrict__ cw,
                           const float* __restrict__ cb,
                           float* __restrict__ pred_out) {
    int row = blockIdx.x * blockDim.x + threadIdx.x;
    if (row >= NU) return;
    const float* s = (row == 0) ? g_sutt : (g_q + (row - 1)*DOUT);
    float lg[NC];
    #pragma unroll
    for (int c = 0; c < NC; c++) {
        float acc = cb[c];
        const float* wr = cw + c*DOUT;
        #pragma unroll 4
        for (int k = 0; k < DOUT; k++) acc += s[k] * wr[k];
        lg[c] = acc;
    }
    float mx = lg[0];
    #pragma unroll
    for (int c = 1; c < NC; c++) mx = fmaxf(mx, lg[c]);
    float sum = 0.f;
    #pragma unroll
    for (int c = 0; c < NC; c++) sum += expf(lg[c] - mx);
    float lse = mx + logf(sum);
    #pragma unroll
    for (int c = 0; c < NC; c++) pred_out[row*NC + c] = lg[c] - lse;
}

// ---------------- launch sequence ----------------
extern "C" void kernel_launch(void* const* d_in, const int* in_sizes, int n_in,
                              void* d_out, int out_size) {
    const int*   sents   = (const int*)  d_in[0];
    const float* emb     = (const float*)d_in[2];
    const float* trans_w = (const float*)d_in[3];
    const float* trans_b = (const float*)d_in[4];
    const float* gru_wih = (const float*)d_in[5];
    const float* gru_whh = (const float*)d_in[6];
    const float* gru_bih = (const float*)d_in[7];
    const float* gru_bhh = (const float*)d_in[8];
    const float* cls_w   = (const float*)d_in[9];
    const float* cls_b   = (const float*)d_in[10];
    const float* conv_w3 = (const float*)d_in[11];
    const float* conv_b3 = (const float*)d_in[12];
    const float* conv_w4 = (const float*)d_in[13];
    const float* conv_b4 = (const float*)d_in[14];
    const float* conv_w5 = (const float*)d_in[15];
    const float* conv_b5 = (const float*)d_in[16];

    float* outF = (float*)d_out;
    float* pred_out = outF;
    float* attn_out;
    if (out_size >= NU*NC + HOPS*NB*WIND) attn_out = outF + NU*NC;
    else cudaGetSymbolAddress((void**)&attn_out, g_attn_scratch);

    cudaFuncSetAttribute(conv_gemm_mma, cudaFuncAttributeMaxDynamicSharedMemorySize, GEMM_SMEM);
    cudaFuncSetAttribute(gru_fused,     cudaFuncAttributeMaxDynamicSharedMemorySize, GRU_SMEM);

    pack_At<<<(int)(((size_t)VPAD*KPAD/4 + 255)/256), 256>>>(emb);
    pack_wallT<<<(NCOL*KPAD/2 + 255)/256, 256>>>(conv_w3, conv_w4, conv_w5);
    transpose_tw<<<(FCAT*DOUT + 255)/256, 256>>>(trans_w);

    dim3 ggrid(NCOL/256, VPAD/128);   // (3, 391)
    conv_gemm_mma<<<ggrid, 512, GEMM_SMEM>>>();

    poolsutt_kernel<<<NU, 384>>>(sents, conv_b3, conv_b4, conv_b5, trans_b);
    xproj_kernel<<<(NB + 15)/16, 256>>>(gru_wih, gru_bih);
    gru_fused<<<(NB + 15)/16, 256, GRU_SMEM>>>(gru_whh, gru_bhh, gru_bih);

    attn_kernel<<<NB, 128>>>(attn_out);
    cls_kernel<<<(NU + 255)/256, 256>>>(cls_w, cls_b, pred_out);
}

// round 6
// speedup vs baseline: 4.9889x; 1.0349x over previous
#include <cuda_runtime.h>
#include <cuda_fp16.h>
#include <math.h>
#include <stdint.h>

// ---------------- problem constants ----------------
#define NU    2048
#define SL    50
#define DE    300
#define KPAD  320      // 40 k-groups of 8; 10 chunks of 32
#define DOUT  100
#define NC    7
#define WIND  10
#define HOPS  3
#define NB    2047
#define VOCAB 50000
#define VPAD  50048    // 391 * 128
#define NCOL  768
#define FCAT  192

// ---------------- static scratch ----------------
// g_At: A fragment order: f4[((mblk*40 + kc8)*8 + r16)*32 + lane]
__device__ float g_At[(size_t)VPAD*KPAD];
// g_WallT: B nt-pair fragment order: f4[((nblk*40 + kc8)*16 + np)*32 + lane]
__device__ float g_WallT[NCOL*KPAD];
__device__ __half g_Zh[(size_t)VPAD*NCOL];      // fp16 projections (77 MB)
__device__ float g_twT[FCAT*DOUT];
__device__ float g_sutt[NU*DOUT];
__device__ float g_xproj[NB*3*DOUT];
__device__ float g_memb[NB*WIND*DOUT];
__device__ float g_q[NB*DOUT];
__device__ float g_attn_scratch[HOPS*NB*WIND];

// ---------------- helpers ----------------
__device__ __forceinline__ uint32_t smem_u32(const void* p) {
    uint32_t a;
    asm("{ .reg .u64 t; cvta.to.shared.u64 t, %1; cvt.u32.u64 %0, t; }" : "=r"(a) : "l"(p));
    return a;
}
__device__ __forceinline__ float to_tf32(float x) {
    float r; asm("cvt.rna.tf32.f32 %0, %1;" : "=f"(r) : "f"(x)); return r;
}
#define CP_ASYNC16(sa, gp) asm volatile("cp.async.cg.shared.global [%0], [%1], 16;" :: "r"(sa), "l"(gp) : "memory")
#define CP_COMMIT()        asm volatile("cp.async.commit_group;" ::: "memory")
#define CP_WAIT(n)         asm volatile("cp.async.wait_group %0;" :: "n"(n) : "memory")

__device__ __forceinline__ void mma_tf32(float* d, const uint32_t* a, const uint32_t* b) {
    asm volatile("mma.sync.aligned.m16n8k8.row.col.f32.tf32.tf32.f32 "
        "{%0,%1,%2,%3}, {%4,%5,%6,%7}, {%8,%9}, {%0,%1,%2,%3};"
        : "+f"(d[0]), "+f"(d[1]), "+f"(d[2]), "+f"(d[3])
        : "r"(a[0]), "r"(a[1]), "r"(a[2]), "r"(a[3]), "r"(b[0]), "r"(b[1]));
}

// ---------------- pack A (dst-linear, fragment order) ----------------
__device__ __forceinline__ float emb_at(const float* emb, int m, int k) {
    if (m >= VOCAB || k >= DE) return 0.f;
    return to_tf32(emb[(size_t)m*DE + k]);
}
__global__ void pack_At(const float* __restrict__ emb) {
    size_t d4 = (size_t)blockIdx.x * blockDim.x + threadIdx.x;
    if (d4 >= (size_t)VPAD*KPAD/4) return;
    int lane = (int)(d4 & 31);
    int r16  = (int)((d4 >> 5) & 7);
    size_t rest = d4 >> 8;
    int kc8  = (int)(rest % 40);
    int mblk = (int)(rest / 40);
    int m = mblk*128 + r16*16 + (lane >> 2);
    int k = kc8*8 + (lane & 3);
    float4 v = make_float4(emb_at(emb, m, k),     emb_at(emb, m + 8, k),
                           emb_at(emb, m, k + 4), emb_at(emb, m + 8, k + 4));
    reinterpret_cast<float4*>(g_At)[d4] = v;
}

// ---------------- pack B (dst-linear, nt-pair fragment order) ----------------
__device__ __forceinline__ float wall_at(const float* w3, const float* w4,
                                         const float* w5, int c, int k) {
    if (k >= DE) return 0.f;
    float v;
    if (c < 192)      { int cc = c;       int dt = cc >> 6, o = cc & 63; v = w3[(o*3 + dt)*DE + k]; }
    else if (c < 448) { int cc = c - 192; int dt = cc >> 6, o = cc & 63; v = w4[(o*4 + dt)*DE + k]; }
    else              { int cc = c - 448; int dt = cc >> 6, o = cc & 63; v = w5[(o*5 + dt)*DE + k]; }
    return to_tf32(v);
}
__global__ void pack_wallT(const float* __restrict__ w3,
                           const float* __restrict__ w4,
                           const float* __restrict__ w5) {
    int d4 = blockIdx.x * blockDim.x + threadIdx.x;
    if (d4 >= NCOL*KPAD/4) return;
    int lane = d4 & 31;
    int np   = (d4 >> 5) & 15;
    int rest = d4 >> 9;
    int kc8  = rest % 40;
    int nblk = rest / 40;
    int n_a = nblk*256 + np*16 + (lane >> 2);   // first n8 group of the pair
    int n_b = n_a + 8;                          // second n8 group
    int k = kc8*8 + (lane & 3);
    float4 v = make_float4(wall_at(w3, w4, w5, n_a, k), wall_at(w3, w4, w5, n_a, k + 4),
                           wall_at(w3, w4, w5, n_b, k), wall_at(w3, w4, w5, n_b, k + 4));
    reinterpret_cast<float4*>(g_WallT)[d4] = v;
}

__global__ void transpose_tw(const float* __restrict__ tw) {
    int idx = blockIdx.x * blockDim.x + threadIdx.x;
    if (idx >= FCAT*DOUT) return;
    int j = idx / DOUT, d = idx % DOUT;
    g_twT[idx] = tw[d*FCAT + j];
}

// ---------------- tf32 mma GEMM: Z = At @ WallT^T (fp16 out) ----------------
// CTA 128(M) x 256(N), 512 thr = 16 warps (4x4), warp tile 32x64.
// K = 10 chunks of 32. 3-stage cp.async pipeline, ONE syncthreads per chunk.
// smem floats: A stages [0,12288) of 4096 each; B stages [12288,36864) of 8192 each.
#define GEMM_SMEM (36864*4)

__global__ void __launch_bounds__(512, 1) conv_gemm_mma() {
    extern __shared__ float sm[];
    const int tid  = threadIdx.x;
    const int lane = tid & 31, wid = tid >> 5;
    const int warp_m = wid & 3;
    const int warp_n = wid >> 2;
    const int by = blockIdx.y, bx = blockIdx.x;
    const int m0 = by * 128, n0 = bx * 256;

    const uint32_t smb = smem_u32(sm);
    const float4* At4 = reinterpret_cast<const float4*>(g_At);
    const float4* Bt4 = reinterpret_cast<const float4*>(g_WallT);

    float acc[2][8][4];
    #pragma unroll
    for (int mt = 0; mt < 2; mt++)
        #pragma unroll
        for (int nt = 0; nt < 8; nt++)
            #pragma unroll
            for (int i = 0; i < 4; i++) acc[mt][nt][i] = 0.f;

    // prologue: stage chunks 0 and 1
    #pragma unroll
    for (int c = 0; c < 2; c++) {
        size_t aG = ((size_t)by*40 + c*4) * 256;   // f4 per chunk: 1024
        size_t bG = ((size_t)bx*40 + c*4) * 512;   // f4 per chunk: 2048
        #pragma unroll
        for (int i = 0; i < 2; i++)
            CP_ASYNC16(smb + c*16384 + (tid + i*512)*16, At4 + aG + tid + i*512);
        #pragma unroll
        for (int i = 0; i < 4; i++)
            CP_ASYNC16(smb + 49152 + c*32768 + (tid + i*512)*16, Bt4 + bG + tid + i*512);
        CP_COMMIT();
    }

    for (int c = 0; c < 10; c++) {
        const int buf = c % 3;
        if (c < 9) CP_WAIT(1); else CP_WAIT(0);
        __syncthreads();
        if (c + 2 < 10) {
            const int nb = (c + 2) % 3;
            size_t aG = ((size_t)by*40 + (c + 2)*4) * 256;
            size_t bG = ((size_t)bx*40 + (c + 2)*4) * 512;
            #pragma unroll
            for (int i = 0; i < 2; i++)
                CP_ASYNC16(smb + nb*16384 + (tid + i*512)*16, At4 + aG + tid + i*512);
            #pragma unroll
            for (int i = 0; i < 4; i++)
                CP_ASYNC16(smb + 49152 + nb*32768 + (tid + i*512)*16, Bt4 + bG + tid + i*512);
            CP_COMMIT();
        }

        const float4* A4 = reinterpret_cast<const float4*>(sm + buf*4096);
        const float4* B4 = reinterpret_cast<const float4*>(sm + 12288 + buf*8192);
        #pragma unroll
        for (int ks = 0; ks < 4; ks++) {
            uint32_t a[2][4], b[8][2];
            #pragma unroll
            for (int mt = 0; mt < 2; mt++) {
                float4 v = A4[(ks*8 + warp_m*2 + mt)*32 + lane];
                a[mt][0] = __float_as_uint(v.x); a[mt][1] = __float_as_uint(v.y);
                a[mt][2] = __float_as_uint(v.z); a[mt][3] = __float_as_uint(v.w);
            }
            #pragma unroll
            for (int np = 0; np < 4; np++) {
                float4 u = B4[(ks*16 + warp_n*4 + np)*32 + lane];
                b[2*np  ][0] = __float_as_uint(u.x); b[2*np  ][1] = __float_as_uint(u.y);
                b[2*np+1][0] = __float_as_uint(u.z); b[2*np+1][1] = __float_as_uint(u.w);
            }
            #pragma unroll
            for (int mt = 0; mt < 2; mt++)
                #pragma unroll
                for (int nt = 0; nt < 8; nt++)
                    mma_tf32(acc[mt][nt], a[mt], b[nt]);
        }
    }

    // epilogue -> fp16
    __half2* Z2 = reinterpret_cast<__half2*>(g_Zh);
    #pragma unroll
    for (int mt = 0; mt < 2; mt++) {
        int r = m0 + warp_m*32 + mt*16 + (lane >> 2);
        #pragma unroll
        for (int nt = 0; nt < 8; nt++) {
            int cc = n0 + warp_n*64 + nt*8 + (lane & 3)*2;
            Z2[((size_t) r      *NCOL + cc) >> 1] = __floats2half2_rn(acc[mt][nt][0], acc[mt][nt][1]);
            Z2[((size_t)(r + 8)*NCOL + cc) >> 1] = __floats2half2_rn(acc[mt][nt][2], acc[mt][nt][3]);
        }
    }
}

// ---------------- fused pool + relu + tanh projection (2-way t-split) -------
__global__ void __launch_bounds__(384) poolsutt_kernel(
        const int* __restrict__ sents,
        const float* __restrict__ b3, const float* __restrict__ b4,
        const float* __restrict__ b5, const float* __restrict__ tb) {
    __shared__ int   toks[SL];
    __shared__ float pmax[384];
    __shared__ float fsh[FCAT];
    const int n = blockIdx.x;
    const int tid = threadIdx.x;

    if (tid < SL) toks[tid] = sents[n*SL + tid];
    __syncthreads();
    {
        const int half = tid / FCAT;
        const int f = tid - half*FCAT;
        const int fi = f >> 6, o = f & 63;
        const int fs  = 3 + fi;
        const int off = (fi == 0) ? 0 : (fi == 1) ? 192 : 448;
        const int T = SL - fs + 1;
        const int t0 = half ? (T >> 1) : 0;
        const int t1 = half ? T : (T >> 1);
        float mx = -1e30f;
        for (int t = t0; t < t1; t++) {
            float v = 0.f;
            #pragma unroll 5
            for (int dt = 0; dt < fs; dt++)
                v += __half2float(g_Zh[(size_t)toks[t + dt]*NCOL + off + dt*64 + o]);
            mx = fmaxf(mx, v);
        }
        pmax[tid] = mx;
    }
    __syncthreads();
    if (tid < FCAT) {
        int fi = tid >> 6, o = tid & 63;
        float bias = (fi == 0) ? b3[o] : (fi == 1) ? b4[o] : b5[o];
        float mx = fmaxf(pmax[tid], pmax[tid + FCAT]);
        fsh[tid] = fmaxf(0.f, mx + bias);
    }
    __syncthreads();
    if (tid < DOUT) {
        float acc = tb[tid];
        #pragma unroll 8
        for (int j = 0; j < FCAT; j++) acc += fsh[j] * g_twT[j*DOUT + tid];
        g_sutt[n*DOUT + tid] = tanhf(acc);
    }
}

// ---------------- GRU input projection ----------------
__global__ void __launch_bounds__(256) xproj_kernel(
        const float* __restrict__ wih, const float* __restrict__ bih) {
    __shared__ float ss[16][DOUT];
    const int tid = threadIdx.x;
    const int v0 = blockIdx.x * 16;
    for (int idx = tid; idx < 16*DOUT; idx += 256) {
        int r = idx / DOUT, d = idx % DOUT;
        int v = v0 + r;
        ss[r][d] = (v < NB) ? g_sutt[v*DOUT + d] : 0.f;
    }
    __syncthreads();
    for (int idx = tid; idx < 16*3*DOUT; idx += 256) {
        int j = idx >> 4, r = idx & 15;
        int v = v0 + r;
        if (v >= NB) continue;
        const float4* wI = reinterpret_cast<const float4*>(wih + j*DOUT);
        const float4* xv = reinterpret_cast<const float4*>(ss[r]);
        float acc = 0.f;
        #pragma unroll
        for (int k = 0; k < DOUT/4; k++) {
            float4 w = wI[k], x = xv[k];
            acc += w.x*x.x + w.y*x.y + w.z*x.z + w.w*x.w;
        }
        g_xproj[v*3*DOUT + j] = acc + bih[j];
    }
}

// ---------------- fused GRU: all 10 steps, whh resident in smem ----------------
#define GRU_SMEM ((30000 + 300 + 300 + 1600 + 4800) * 4)
__global__ void __launch_bounds__(256) gru_fused(
        const float* __restrict__ whh, const float* __restrict__ bhh,
        const float* __restrict__ bih) {
    extern __shared__ float smg[];
    float* whh_s = smg;
    float* bhh_s = smg + 30000;
    float* bih_s = bhh_s + 300;
    float* hs    = bih_s + 300;        // [16][100]
    float* gh    = hs + 1600;          // [16][300]
    const int tid = threadIdx.x;
    const int b0 = blockIdx.x * 16;

    for (int i = tid; i < 30000; i += 256) whh_s[i] = whh[i];
    for (int i = tid; i < 300; i += 256) { bhh_s[i] = bhh[i]; bih_s[i] = bih[i]; }
    for (int i = tid; i < 1600; i += 256) hs[i] = 0.f;
    __syncthreads();

    for (int s = 0; s < WIND; s++) {
        for (int idx = tid; idx < 16*3*DOUT; idx += 256) {
            int j = idx >> 4, r = idx & 15;
            const float4* wH = reinterpret_cast<const float4*>(whh_s + j*DOUT);
            const float4* hv = reinterpret_cast<const float4*>(hs + r*DOUT);
            float acc = 0.f;
            #pragma unroll
            for (int k = 0; k < DOUT/4; k++) {
                float4 w = wH[k], h = hv[k];
                acc += w.x*h.x + w.y*h.y + w.z*h.z + w.w*h.w;
            }
            gh[r*3*DOUT + j] = acc + bhh_s[j];
        }
        __syncthreads();
        for (int idx = tid; idx < 16*DOUT; idx += 256) {
            int r = idx / DOUT, d = idx % DOUT;
            int b = b0 + r;
            if (b >= NB) continue;
            int src = b + s - (WIND - 1);
            float giR, giZ, giN, xv;
            if (src >= 0) {
                const float* xp = g_xproj + src*3*DOUT;
                giR = xp[d]; giZ = xp[DOUT + d]; giN = xp[2*DOUT + d];
                xv = g_sutt[src*DOUT + d];
            } else {
                giR = bih_s[d]; giZ = bih_s[DOUT + d]; giN = bih_s[2*DOUT + d];
                xv = 0.f;
            }
            float hr = gh[r*3*DOUT + d], hz = gh[r*3*DOUT + DOUT + d], hn = gh[r*3*DOUT + 2*DOUT + d];
            float rr = 1.f / (1.f + expf(-(giR + hr)));
            float zz = 1.f / (1.f + expf(-(giZ + hz)));
            float nn = tanhf(giN + rr*hn);
            float hnew = (1.f - zz)*nn + zz*hs[r*DOUT + d];
            hs[r*DOUT + d] = hnew;
            g_memb[(b*WIND + s)*DOUT + d] = xv + hnew;
        }
        __syncthreads();
    }
}

// ---------------- 3-hop attention ----------------
__global__ void attn_kernel(float* __restrict__ attn_out) {
    __shared__ float M[WIND][DOUT];
    __shared__ float q[DOUT];
    __shared__ float l[WIND];
    __shared__ float a[WIND];
    const int b = blockIdx.x;
    const int tid = threadIdx.x;

    for (int idx = tid; idx < WIND*DOUT; idx += blockDim.x)
        M[idx/DOUT][idx%DOUT] = g_memb[(b*WIND)*DOUT + idx];
    if (tid < DOUT) q[tid] = g_sutt[(b+1)*DOUT + tid];
    __syncthreads();

    for (int hop = 0; hop < HOPS; hop++) {
        if (tid < WIND) {
            float acc = 0.f;
            #pragma unroll 4
            for (int d = 0; d < DOUT; d++) acc += q[d] * M[tid][d];
            bool valid = (b + tid - (WIND - 1)) >= 0;
            l[tid] = valid ? acc : -1e10f;
        }
        __syncthreads();
        if (tid == 0) {
            float mx = -1e30f;
            for (int k = 0; k < WIND; k++) mx = fmaxf(mx, l[k]);
            float sum = 0.f;
            for (int k = 0; k < WIND; k++) { a[k] = expf(l[k] - mx); sum += a[k]; }
            float inv = 1.f / sum;
            for (int k = 0; k < WIND; k++) a[k] *= inv;
        }
        __syncthreads();
        if (tid < WIND)
            attn_out[hop*(NB*WIND) + b*WIND + tid] = a[tid];
        if (tid < DOUT) {
            float acc = 0.f;
            #pragma unroll
            for (int k = 0; k < WIND; k++) acc += a[k] * M[k][tid];
            q[tid] += acc;
        }
        __syncthreads();
    }
    if (tid < DOUT) g_q[b*DOUT + tid] = q[tid];
}

// ---------------- classifier + log_softmax ----------------
__global__ void cls_kernel(const float* __restrict__ cw,
                           const float* __restrict__ cb,
                           float* __restrict__ pred_out) {
    int row = blockIdx.x * blockDim.x + threadIdx.x;
    if (row >= NU) return;
    const float* s = (row == 0) ? g_sutt : (g_q + (row - 1)*DOUT);
    float lg[NC];
    #pragma unroll
    for (int c = 0; c < NC; c++) {
        float acc = cb[c];
        const float* wr = cw + c*DOUT;
        #pragma unroll 4
        for (int k = 0; k < DOUT; k++) acc += s[k] * wr[k];
        lg[c] = acc;
    }
    float mx = lg[0];
    #pragma unroll
    for (int c = 1; c < NC; c++) mx = fmaxf(mx, lg[c]);
    float sum = 0.f;
    #pragma unroll
    for (int c = 0; c < NC; c++) sum += expf(lg[c] - mx);
    float lse = mx + logf(sum);
    #pragma unroll
    for (int c = 0; c < NC; c++) pred_out[row*NC + c] = lg[c] - lse;
}

// ---------------- launch sequence ----------------
extern "C" void kernel_launch(void* const* d_in, const int* in_sizes, int n_in,
                              void* d_out, int out_size) {
    const int*   sents   = (const int*)  d_in[0];
    const float* emb     = (const float*)d_in[2];
    const float* trans_w = (const float*)d_in[3];
    const float* trans_b = (const float*)d_in[4];
    const float* gru_wih = (const float*)d_in[5];
    const float* gru_whh = (const float*)d_in[6];
    const float* gru_bih = (const float*)d_in[7];
    const float* gru_bhh = (const float*)d_in[8];
    const float* cls_w   = (const float*)d_in[9];
    const float* cls_b   = (const float*)d_in[10];
    const float* conv_w3 = (const float*)d_in[11];
    const float* conv_b3 = (const float*)d_in[12];
    const float* conv_w4 = (const float*)d_in[13];
    const float* conv_b4 = (const float*)d_in[14];
    const float* conv_w5 = (const float*)d_in[15];
    const float* conv_b5 = (const float*)d_in[16];

    float* outF = (float*)d_out;
    float* pred_out = outF;
    float* attn_out;
    if (out_size >= NU*NC + HOPS*NB*WIND) attn_out = outF + NU*NC;
    else cudaGetSymbolAddress((void**)&attn_out, g_attn_scratch);

    cudaFuncSetAttribute(conv_gemm_mma, cudaFuncAttributeMaxDynamicSharedMemorySize, GEMM_SMEM);
    cudaFuncSetAttribute(gru_fused,     cudaFuncAttributeMaxDynamicSharedMemorySize, GRU_SMEM);

    pack_At<<<(int)(((size_t)VPAD*KPAD/4 + 255)/256), 256>>>(emb);
    pack_wallT<<<(NCOL*KPAD/4 + 255)/256, 256>>>(conv_w3, conv_w4, conv_w5);
    transpose_tw<<<(FCAT*DOUT + 255)/256, 256>>>(trans_w);

    dim3 ggrid(NCOL/256, VPAD/128);   // (3, 391)
    conv_gemm_mma<<<ggrid, 512, GEMM_SMEM>>>();

    poolsutt_kernel<<<NU, 384>>>(sents, conv_b3, conv_b4, conv_b5, trans_b);
    xproj_kernel<<<(NB + 15)/16, 256>>>(gru_wih, gru_bih);
    gru_fused<<<(NB + 15)/16, 256, GRU_SMEM>>>(gru_whh, gru_bhh, gru_bih);

    attn_kernel<<<NB, 128>>>(attn_out);
    cls_kernel<<<(NU + 255)/256, 256>>>(cls_w, cls_b, pred_out);
}

// round 7
// speedup vs baseline: 5.8764x; 1.1779x over previous
#include <cuda_runtime.h>
#include <cuda_fp16.h>
#include <math.h>
#include <stdint.h>

// ---------------- problem constants ----------------
#define NU    2048
#define SL    50
#define DE    300
#define KPAD  320      // 20 k-groups of 16; 10 chunks of 32
#define DOUT  100
#define NC    7
#define WIND  10
#define HOPS  3
#define NB    2047
#define VOCAB 50000
#define VPAD  50048    // 391 * 128
#define NCOL  768
#define FCAT  192

// ---------------- static scratch ----------------
// g_Ah: A fp16 fragment order: u4[((mblk*20 + kc16)*8 + r16)*32 + lane]
//   u4 = {A[m][k],A[m][k+1]} {A[m+8][k..]} {A[m][k+8..]} {A[m+8][k+8..]}
__device__ __half g_Ah[(size_t)VPAD*KPAD];
// g_Bh: B fp16 nt-pair fragment order: u4[((nblk*20 + kc16)*16 + np)*32 + lane]
//   u4 = {W[na][k..k+1]} {W[na][k+8..k+9]} {W[nb][k..k+1]} {W[nb][k+8..k+9]}
__device__ __half g_Bh[NCOL*KPAD];
__device__ __half g_Zh[(size_t)VPAD*NCOL];      // fp16 projections (77 MB)
__device__ float g_twT[FCAT*DOUT];
__device__ float g_sutt[NU*DOUT];
__device__ float g_xproj[NB*3*DOUT];
__device__ float g_memb[NB*WIND*DOUT];
__device__ float g_q[NB*DOUT];
__device__ float g_attn_scratch[HOPS*NB*WIND];

// ---------------- helpers ----------------
__device__ __forceinline__ uint32_t smem_u32(const void* p) {
    uint32_t a;
    asm("{ .reg .u64 t; cvta.to.shared.u64 t, %1; cvt.u32.u64 %0, t; }" : "=r"(a) : "l"(p));
    return a;
}
#define CP_ASYNC16(sa, gp) asm volatile("cp.async.cg.shared.global [%0], [%1], 16;" :: "r"(sa), "l"(gp) : "memory")
#define CP_COMMIT()        asm volatile("cp.async.commit_group;" ::: "memory")
#define CP_WAIT(n)         asm volatile("cp.async.wait_group %0;" :: "n"(n) : "memory")

__device__ __forceinline__ void mma_fp16(float* d, const uint32_t* a, const uint32_t* b) {
    asm volatile("mma.sync.aligned.m16n8k16.row.col.f32.f16.f16.f32 "
        "{%0,%1,%2,%3}, {%4,%5,%6,%7}, {%8,%9}, {%0,%1,%2,%3};"
        : "+f"(d[0]), "+f"(d[1]), "+f"(d[2]), "+f"(d[3])
        : "r"(a[0]), "r"(a[1]), "r"(a[2]), "r"(a[3]), "r"(b[0]), "r"(b[1]));
}

// ---------------- pack A (dst-linear, fp16 fragment order) ----------------
__device__ __forceinline__ __half emb_h(const float* emb, int m, int k) {
    if (m >= VOCAB || k >= DE) return __float2half_rn(0.f);
    return __float2half_rn(emb[(size_t)m*DE + k]);
}
__global__ void pack_Ah(const float* __restrict__ emb) {
    size_t d4 = (size_t)blockIdx.x * blockDim.x + threadIdx.x;   // uint4 index (8 fp16)
    if (d4 >= (size_t)VPAD*KPAD/8) return;
    int lane = (int)(d4 & 31);
    int r16  = (int)((d4 >> 5) & 7);
    size_t rest = d4 >> 8;
    int kc16 = (int)(rest % 20);
    int mblk = (int)(rest / 20);
    int m = mblk*128 + r16*16 + (lane >> 2);
    int k = kc16*16 + (lane & 3)*2;
    __half2 h0 = __halves2half2(emb_h(emb, m,     k),     emb_h(emb, m,     k + 1));
    __half2 h1 = __halves2half2(emb_h(emb, m + 8, k),     emb_h(emb, m + 8, k + 1));
    __half2 h2 = __halves2half2(emb_h(emb, m,     k + 8), emb_h(emb, m,     k + 9));
    __half2 h3 = __halves2half2(emb_h(emb, m + 8, k + 8), emb_h(emb, m + 8, k + 9));
    uint4 v = make_uint4(*(uint32_t*)&h0, *(uint32_t*)&h1, *(uint32_t*)&h2, *(uint32_t*)&h3);
    reinterpret_cast<uint4*>(g_Ah)[d4] = v;
}

// ---------------- pack B (dst-linear, fp16 nt-pair fragment order) -----------
__device__ __forceinline__ __half wall_h(const float* w3, const float* w4,
                                         const float* w5, int c, int k) {
    if (k >= DE) return __float2half_rn(0.f);
    float v;
    if (c < 192)      { int cc = c;       int dt = cc >> 6, o = cc & 63; v = w3[(o*3 + dt)*DE + k]; }
    else if (c < 448) { int cc = c - 192; int dt = cc >> 6, o = cc & 63; v = w4[(o*4 + dt)*DE + k]; }
    else              { int cc = c - 448; int dt = cc >> 6, o = cc & 63; v = w5[(o*5 + dt)*DE + k]; }
    return __float2half_rn(v);
}
__global__ void pack_Bh(const float* __restrict__ w3,
                        const float* __restrict__ w4,
                        const float* __restrict__ w5) {
    int d4 = blockIdx.x * blockDim.x + threadIdx.x;
    if (d4 >= NCOL*KPAD/8) return;
    int lane = d4 & 31;
    int np   = (d4 >> 5) & 15;
    int rest = d4 >> 9;
    int kc16 = rest % 20;
    int nblk = rest / 20;
    int na = nblk*256 + np*16 + (lane >> 2);
    int nb = na + 8;
    int k = kc16*16 + (lane & 3)*2;
    __half2 h0 = __halves2half2(wall_h(w3,w4,w5, na, k),     wall_h(w3,w4,w5, na, k + 1));
    __half2 h1 = __halves2half2(wall_h(w3,w4,w5, na, k + 8), wall_h(w3,w4,w5, na, k + 9));
    __half2 h2 = __halves2half2(wall_h(w3,w4,w5, nb, k),     wall_h(w3,w4,w5, nb, k + 1));
    __half2 h3 = __halves2half2(wall_h(w3,w4,w5, nb, k + 8), wall_h(w3,w4,w5, nb, k + 9));
    uint4 v = make_uint4(*(uint32_t*)&h0, *(uint32_t*)&h1, *(uint32_t*)&h2, *(uint32_t*)&h3);
    reinterpret_cast<uint4*>(g_Bh)[d4] = v;
}

__global__ void transpose_tw(const float* __restrict__ tw) {
    int idx = blockIdx.x * blockDim.x + threadIdx.x;
    if (idx >= FCAT*DOUT) return;
    int j = idx / DOUT, d = idx % DOUT;
    g_twT[idx] = tw[d*FCAT + j];
}

// ---------------- fp16 mma GEMM: Z = Ah @ Bh^T (fp16 out) ----------------
// CTA 128(M) x 256(N), 512 thr = 16 warps (4x4), warp tile 32x64.
// K = 10 chunks of 32 (2 x k16 per chunk). 3-stage cp.async, one sync per chunk.
// smem bytes: A stages 3 x 8192 at [0,24576); B stages 3 x 16384 at [24576,73728)
#define GEMM_SMEM 73728

__global__ void __launch_bounds__(512, 1) conv_gemm_mma() {
    extern __shared__ char smc[];
    const int tid  = threadIdx.x;
    const int lane = tid & 31, wid = tid >> 5;
    const int warp_m = wid & 3;
    const int warp_n = wid >> 2;
    const int by = blockIdx.y, bx = blockIdx.x;
    const int m0 = by * 128, n0 = bx * 256;

    const uint32_t smb = smem_u32(smc);
    const uint4* Ah4 = reinterpret_cast<const uint4*>(g_Ah);
    const uint4* Bh4 = reinterpret_cast<const uint4*>(g_Bh);

    float acc[2][8][4];
    #pragma unroll
    for (int mt = 0; mt < 2; mt++)
        #pragma unroll
        for (int nt = 0; nt < 8; nt++)
            #pragma unroll
            for (int i = 0; i < 4; i++) acc[mt][nt][i] = 0.f;

    // prologue: stage chunks 0,1  (chunk = 2 kc16 => A 512 u4, B 1024 u4)
    #pragma unroll
    for (int c = 0; c < 2; c++) {
        size_t aG = ((size_t)by*20 + c*2) * 256;
        size_t bG = ((size_t)bx*20 + c*2) * 512;
        CP_ASYNC16(smb + c*8192 + tid*16, Ah4 + aG + tid);
        #pragma unroll
        for (int i = 0; i < 2; i++)
            CP_ASYNC16(smb + 24576 + c*16384 + (tid + i*512)*16, Bh4 + bG + tid + i*512);
        CP_COMMIT();
    }

    for (int c = 0; c < 10; c++) {
        const int buf = c % 3;
        if (c < 9) CP_WAIT(1); else CP_WAIT(0);
        __syncthreads();
        if (c + 2 < 10) {
            const int nb = (c + 2) % 3;
            size_t aG = ((size_t)by*20 + (c + 2)*2) * 256;
            size_t bG = ((size_t)bx*20 + (c + 2)*2) * 512;
            CP_ASYNC16(smb + nb*8192 + tid*16, Ah4 + aG + tid);
            #pragma unroll
            for (int i = 0; i < 2; i++)
                CP_ASYNC16(smb + 24576 + nb*16384 + (tid + i*512)*16, Bh4 + bG + tid + i*512);
            CP_COMMIT();
        }

        const uint4* A4 = reinterpret_cast<const uint4*>(smc + buf*8192);
        const uint4* B4 = reinterpret_cast<const uint4*>(smc + 24576 + buf*16384);
        #pragma unroll
        for (int ks = 0; ks < 2; ks++) {           // two k16 steps per chunk
            uint32_t a[2][4], b[8][2];
            #pragma unroll
            for (int mt = 0; mt < 2; mt++) {
                uint4 v = A4[(ks*8 + warp_m*2 + mt)*32 + lane];
                a[mt][0] = v.x; a[mt][1] = v.y; a[mt][2] = v.z; a[mt][3] = v.w;
            }
            #pragma unroll
            for (int np = 0; np < 4; np++) {
                uint4 u = B4[(ks*16 + warp_n*4 + np)*32 + lane];
                b[2*np  ][0] = u.x; b[2*np  ][1] = u.y;
                b[2*np+1][0] = u.z; b[2*np+1][1] = u.w;
            }
            #pragma unroll
            for (int mt = 0; mt < 2; mt++)
                #pragma unroll
                for (int nt = 0; nt < 8; nt++)
                    mma_fp16(acc[mt][nt], a[mt], b[nt]);
        }
    }

    // epilogue -> fp16
    __half2* Z2 = reinterpret_cast<__half2*>(g_Zh);
    #pragma unroll
    for (int mt = 0; mt < 2; mt++) {
        int r = m0 + warp_m*32 + mt*16 + (lane >> 2);
        #pragma unroll
        for (int nt = 0; nt < 8; nt++) {
            int cc = n0 + warp_n*64 + nt*8 + (lane & 3)*2;
            Z2[((size_t) r      *NCOL + cc) >> 1] = __floats2half2_rn(acc[mt][nt][0], acc[mt][nt][1]);
            Z2[((size_t)(r + 8)*NCOL + cc) >> 1] = __floats2half2_rn(acc[mt][nt][2], acc[mt][nt][3]);
        }
    }
}

// ---------------- fused pool + relu + tanh projection (2-way t-split) -------
__global__ void __launch_bounds__(384) poolsutt_kernel(
        const int* __restrict__ sents,
        const float* __restrict__ b3, const float* __restrict__ b4,
        const float* __restrict__ b5, const float* __restrict__ tb) {
    __shared__ int   toks[SL];
    __shared__ float pmax[384];
    __shared__ float fsh[FCAT];
    const int n = blockIdx.x;
    const int tid = threadIdx.x;

    if (tid < SL) toks[tid] = sents[n*SL + tid];
    __syncthreads();
    {
        const int half = tid / FCAT;
        const int f = tid - half*FCAT;
        const int fi = f >> 6, o = f & 63;
        const int fs  = 3 + fi;
        const int off = (fi == 0) ? 0 : (fi == 1) ? 192 : 448;
        const int T = SL - fs + 1;
        const int t0 = half ? (T >> 1) : 0;
        const int t1 = half ? T : (T >> 1);
        float mx = -1e30f;
        for (int t = t0; t < t1; t++) {
            float v = 0.f;
            #pragma unroll 5
            for (int dt = 0; dt < fs; dt++)
                v += __half2float(g_Zh[(size_t)toks[t + dt]*NCOL + off + dt*64 + o]);
            mx = fmaxf(mx, v);
        }
        pmax[tid] = mx;
    }
    __syncthreads();
    if (tid < FCAT) {
        int fi = tid >> 6, o = tid & 63;
        float bias = (fi == 0) ? b3[o] : (fi == 1) ? b4[o] : b5[o];
        float mx = fmaxf(pmax[tid], pmax[tid + FCAT]);
        fsh[tid] = fmaxf(0.f, mx + bias);
    }
    __syncthreads();
    if (tid < DOUT) {
        float acc = tb[tid];
        #pragma unroll 8
        for (int j = 0; j < FCAT; j++) acc += fsh[j] * g_twT[j*DOUT + tid];
        g_sutt[n*DOUT + tid] = tanhf(acc);
    }
}

// ---------------- GRU input projection ----------------
__global__ void __launch_bounds__(256) xproj_kernel(
        const float* __restrict__ wih, const float* __restrict__ bih) {
    __shared__ float ss[16][DOUT];
    const int tid = threadIdx.x;
    const int v0 = blockIdx.x * 16;
    for (int idx = tid; idx < 16*DOUT; idx += 256) {
        int r = idx / DOUT, d = idx % DOUT;
        int v = v0 + r;
        ss[r][d] = (v < NB) ? g_sutt[v*DOUT + d] : 0.f;
    }
    __syncthreads();
    for (int idx = tid; idx < 16*3*DOUT; idx += 256) {
        int j = idx >> 4, r = idx & 15;
        int v = v0 + r;
        if (v >= NB) continue;
        const float4* wI = reinterpret_cast<const float4*>(wih + j*DOUT);
        const float4* xv = reinterpret_cast<const float4*>(ss[r]);
        float acc = 0.f;
        #pragma unroll
        for (int k = 0; k < DOUT/4; k++) {
            float4 w = wI[k], x = xv[k];
            acc += w.x*x.x + w.y*x.y + w.z*x.z + w.w*x.w;
        }
        g_xproj[v*3*DOUT + j] = acc + bih[j];
    }
}

// ---------------- fused GRU: all 10 steps, whh resident in smem ----------------
#define GRU_SMEM ((30000 + 300 + 300 + 1600 + 4800) * 4)
__global__ void __launch_bounds__(256) gru_fused(
        const float* __restrict__ whh, const float* __restrict__ bhh,
        const float* __restrict__ bih) {
    extern __shared__ float smg[];
    float* whh_s = smg;
    float* bhh_s = smg + 30000;
    float* bih_s = bhh_s + 300;
    float* hs    = bih_s + 300;        // [16][100]
    float* gh    = hs + 1600;          // [16][300]
    const int tid = threadIdx.x;
    const int b0 = blockIdx.x * 16;

    for (int i = tid; i < 30000; i += 256) whh_s[i] = whh[i];
    for (int i = tid; i < 300; i += 256) { bhh_s[i] = bhh[i]; bih_s[i] = bih[i]; }
    for (int i = tid; i < 1600; i += 256) hs[i] = 0.f;
    __syncthreads();

    for (int s = 0; s < WIND; s++) {
        for (int idx = tid; idx < 16*3*DOUT; idx += 256) {
            int j = idx >> 4, r = idx & 15;
            const float4* wH = reinterpret_cast<const float4*>(whh_s + j*DOUT);
            const float4* hv = reinterpret_cast<const float4*>(hs + r*DOUT);
            float acc = 0.f;
            #pragma unroll
            for (int k = 0; k < DOUT/4; k++) {
                float4 w = wH[k], h = hv[k];
                acc += w.x*h.x + w.y*h.y + w.z*h.z + w.w*h.w;
            }
            gh[r*3*DOUT + j] = acc + bhh_s[j];
        }
        __syncthreads();
        for (int idx = tid; idx < 16*DOUT; idx += 256) {
            int r = idx / DOUT, d = idx % DOUT;
            int b = b0 + r;
            if (b >= NB) continue;
            int src = b + s - (WIND - 1);
            float giR, giZ, giN, xv;
            if (src >= 0) {
                const float* xp = g_xproj + src*3*DOUT;
                giR = xp[d]; giZ = xp[DOUT + d]; giN = xp[2*DOUT + d];
                xv = g_sutt[src*DOUT + d];
            } else {
                giR = bih_s[d]; giZ = bih_s[DOUT + d]; giN = bih_s[2*DOUT + d];
                xv = 0.f;
            }
            float hr = gh[r*3*DOUT + d], hz = gh[r*3*DOUT + DOUT + d], hn = gh[r*3*DOUT + 2*DOUT + d];
            float rr = 1.f / (1.f + expf(-(giR + hr)));
            float zz = 1.f / (1.f + expf(-(giZ + hz)));
            float nn = tanhf(giN + rr*hn);
            float hnew = (1.f - zz)*nn + zz*hs[r*DOUT + d];
            hs[r*DOUT + d] = hnew;
            g_memb[(b*WIND + s)*DOUT + d] = xv + hnew;
        }
        __syncthreads();
    }
}

// ---------------- 3-hop attention ----------------
__global__ void attn_kernel(float* __restrict__ attn_out) {
    __shared__ float M[WIND][DOUT];
    __shared__ float q[DOUT];
    __shared__ float l[WIND];
    __shared__ float a[WIND];
    const int b = blockIdx.x;
    const int tid = threadIdx.x;

    for (int idx = tid; idx < WIND*DOUT; idx += blockDim.x)
        M[idx/DOUT][idx%DOUT] = g_memb[(b*WIND)*DOUT + idx];
    if (tid < DOUT) q[tid] = g_sutt[(b+1)*DOUT + tid];
    __syncthreads();

    for (int hop = 0; hop < HOPS; hop++) {
        if (tid < WIND) {
            float acc = 0.f;
            #pragma unroll 4
            for (int d = 0; d < DOUT; d++) acc += q[d] * M[tid][d];
            bool valid = (b + tid - (WIND - 1)) >= 0;
            l[tid] = valid ? acc : -1e10f;
        }
        __syncthreads();
        if (tid == 0) {
            float mx = -1e30f;
            for (int k = 0; k < WIND; k++) mx = fmaxf(mx, l[k]);
            float sum = 0.f;
            for (int k = 0; k < WIND; k++) { a[k] = expf(l[k] - mx); sum += a[k]; }
            float inv = 1.f / sum;
            for (int k = 0; k < WIND; k++) a[k] *= inv;
        }
        __syncthreads();
        if (tid < WIND)
            attn_out[hop*(NB*WIND) + b*WIND + tid] = a[tid];
        if (tid < DOUT) {
            float acc = 0.f;
            #pragma unroll
            for (int k = 0; k < WIND; k++) acc += a[k] * M[k][tid];
            q[tid] += acc;
        }
        __syncthreads();
    }
    if (tid < DOUT) g_q[b*DOUT + tid] = q[tid];
}

// ---------------- classifier + log_softmax ----------------
__global__ void cls_kernel(const float* __restrict__ cw,
                           const float* __restrict__ cb,
                           float* __restrict__ pred_out) {
    int row = blockIdx.x * blockDim.x + threadIdx.x;
    if (row >= NU) return;
    const float* s = (row == 0) ? g_sutt : (g_q + (row - 1)*DOUT);
    float lg[NC];
    #pragma unroll
    for (int c = 0; c < NC; c++) {
        float acc = cb[c];
        const float* wr = cw + c*DOUT;
        #pragma unroll 4
        for (int k = 0; k < DOUT; k++) acc += s[k] * wr[k];
        lg[c] = acc;
    }
    float mx = lg[0];
    #pragma unroll
    for (int c = 1; c < NC; c++) mx = fmaxf(mx, lg[c]);
    float sum = 0.f;
    #pragma unroll
    for (int c = 0; c < NC; c++) sum += expf(lg[c] - mx);
    float lse = mx + logf(sum);
    #pragma unroll
    for (int c = 0; c < NC; c++) pred_out[row*NC + c] = lg[c] - lse;
}

// ---------------- launch sequence ----------------
extern "C" void kernel_launch(void* const* d_in, const int* in_sizes, int n_in,
                              void* d_out, int out_size) {
    const int*   sents   = (const int*)  d_in[0];
    const float* emb     = (const float*)d_in[2];
    const float* trans_w = (const float*)d_in[3];
    const float* trans_b = (const float*)d_in[4];
    const float* gru_wih = (const float*)d_in[5];
    const float* gru_whh = (const float*)d_in[6];
    const float* gru_bih = (const float*)d_in[7];
    const float* gru_bhh = (const float*)d_in[8];
    const float* cls_w   = (const float*)d_in[9];
    const float* cls_b   = (const float*)d_in[10];
    const float* conv_w3 = (const float*)d_in[11];
    const float* conv_b3 = (const float*)d_in[12];
    const float* conv_w4 = (const float*)d_in[13];
    const float* conv_b4 = (const float*)d_in[14];
    const float* conv_w5 = (const float*)d_in[15];
    const float* conv_b5 = (const float*)d_in[16];

    float* outF = (float*)d_out;
    float* pred_out = outF;
    float* attn_out;
    if (out_size >= NU*NC + HOPS*NB*WIND) attn_out = outF + NU*NC;
    else cudaGetSymbolAddress((void**)&attn_out, g_attn_scratch);

    cudaFuncSetAttribute(conv_gemm_mma, cudaFuncAttributeMaxDynamicSharedMemorySize, GEMM_SMEM);
    cudaFuncSetAttribute(gru_fused,     cudaFuncAttributeMaxDynamicSharedMemorySize, GRU_SMEM);

    pack_Ah<<<(int)(((size_t)VPAD*KPAD/8 + 255)/256), 256>>>(emb);
    pack_Bh<<<(NCOL*KPAD/8 + 255)/256, 256>>>(conv_w3, conv_w4, conv_w5);
    transpose_tw<<<(FCAT*DOUT + 255)/256, 256>>>(trans_w);

    dim3 ggrid(NCOL/256, VPAD/128);   // (3, 391)
    conv_gemm_mma<<<ggrid, 512, GEMM_SMEM>>>();

    poolsutt_kernel<<<NU, 384>>>(sents, conv_b3, conv_b4, conv_b5, trans_b);
    xproj_kernel<<<(NB + 15)/16, 256>>>(gru_wih, gru_bih);
    gru_fused<<<(NB + 15)/16, 256, GRU_SMEM>>>(gru_whh, gru_bhh, gru_bih);

    attn_kernel<<<NB, 128>>>(attn_out);
    cls_kernel<<<(NU + 255)/256, 256>>>(cls_w, cls_b, pred_out);
}

// round 8
// speedup vs baseline: 5.9312x; 1.0093x over previous
#include <cuda_runtime.h>
#include <cuda_fp16.h>
#include <math.h>
#include <stdint.h>

// ---------------- problem constants ----------------
#define NU    2048
#define SL    50
#define DE    300
#define KPAD  320      // 20 k-groups of 16; 10 chunks of 32
#define DOUT  100
#define NC    7
#define WIND  10
#define HOPS  3
#define NB    2047
#define VOCAB 50000
#define VPAD  50048    // 391 * 128
#define NCOL  768
#define FCAT  192

// ---------------- static scratch ----------------
__device__ __half g_Ah[(size_t)VPAD*KPAD];      // A fp16 fragment order
__device__ __half g_Bh[NCOL*KPAD];              // B fp16 nt-pair fragment order
__device__ __half g_Zh[(size_t)VPAD*NCOL];      // fp16 projections (77 MB)
__device__ float g_twT[FCAT*DOUT];
__device__ float g_sutt[NU*DOUT];
__device__ float g_xproj[NB*3*DOUT];
__device__ float g_memb[NB*WIND*DOUT];
__device__ float g_q[NB*DOUT];
__device__ float g_attn_scratch[HOPS*NB*WIND];

// ---------------- helpers ----------------
__device__ __forceinline__ uint32_t smem_u32(const void* p) {
    uint32_t a;
    asm("{ .reg .u64 t; cvta.to.shared.u64 t, %1; cvt.u32.u64 %0, t; }" : "=r"(a) : "l"(p));
    return a;
}
#define CP_ASYNC16(sa, gp) asm volatile("cp.async.cg.shared.global [%0], [%1], 16;" :: "r"(sa), "l"(gp) : "memory")
#define CP_COMMIT()        asm volatile("cp.async.commit_group;" ::: "memory")
#define CP_WAIT(n)         asm volatile("cp.async.wait_group %0;" :: "n"(n) : "memory")

__device__ __forceinline__ void mma_fp16(float* d, const uint32_t* a, const uint32_t* b) {
    asm volatile("mma.sync.aligned.m16n8k16.row.col.f32.f16.f16.f32 "
        "{%0,%1,%2,%3}, {%4,%5,%6,%7}, {%8,%9}, {%0,%1,%2,%3};"
        : "+f"(d[0]), "+f"(d[1]), "+f"(d[2]), "+f"(d[3])
        : "r"(a[0]), "r"(a[1]), "r"(a[2]), "r"(a[3]), "r"(b[0]), "r"(b[1]));
}

// ---------------- pack A (dst-linear, fp16 fragment order) ----------------
__device__ __forceinline__ __half emb_h(const float* emb, int m, int k) {
    if (m >= VOCAB || k >= DE) return __float2half_rn(0.f);
    return __float2half_rn(emb[(size_t)m*DE + k]);
}
__global__ void pack_Ah(const float* __restrict__ emb) {
    size_t d4 = (size_t)blockIdx.x * blockDim.x + threadIdx.x;
    if (d4 >= (size_t)VPAD*KPAD/8) return;
    int lane = (int)(d4 & 31);
    int r16  = (int)((d4 >> 5) & 7);
    size_t rest = d4 >> 8;
    int kc16 = (int)(rest % 20);
    int mblk = (int)(rest / 20);
    int m = mblk*128 + r16*16 + (lane >> 2);
    int k = kc16*16 + (lane & 3)*2;
    __half2 h0 = __halves2half2(emb_h(emb, m,     k),     emb_h(emb, m,     k + 1));
    __half2 h1 = __halves2half2(emb_h(emb, m + 8, k),     emb_h(emb, m + 8, k + 1));
    __half2 h2 = __halves2half2(emb_h(emb, m,     k + 8), emb_h(emb, m,     k + 9));
    __half2 h3 = __halves2half2(emb_h(emb, m + 8, k + 8), emb_h(emb, m + 8, k + 9));
    uint4 v = make_uint4(*(uint32_t*)&h0, *(uint32_t*)&h1, *(uint32_t*)&h2, *(uint32_t*)&h3);
    reinterpret_cast<uint4*>(g_Ah)[d4] = v;
}

// ---------------- pack B (dst-linear, fp16 nt-pair fragment order) -----------
__device__ __forceinline__ __half wall_h(const float* w3, const float* w4,
                                         const float* w5, int c, int k) {
    if (k >= DE) return __float2half_rn(0.f);
    float v;
    if (c < 192)      { int cc = c;       int dt = cc >> 6, o = cc & 63; v = w3[(o*3 + dt)*DE + k]; }
    else if (c < 448) { int cc = c - 192; int dt = cc >> 6, o = cc & 63; v = w4[(o*4 + dt)*DE + k]; }
    else              { int cc = c - 448; int dt = cc >> 6, o = cc & 63; v = w5[(o*5 + dt)*DE + k]; }
    return __float2half_rn(v);
}
__global__ void pack_Bh(const float* __restrict__ w3,
                        const float* __restrict__ w4,
                        const float* __restrict__ w5) {
    int d4 = blockIdx.x * blockDim.x + threadIdx.x;
    if (d4 >= NCOL*KPAD/8) return;
    int lane = d4 & 31;
    int np   = (d4 >> 5) & 15;
    int rest = d4 >> 9;
    int kc16 = rest % 20;
    int nblk = rest / 20;
    int na = nblk*256 + np*16 + (lane >> 2);
    int nb = na + 8;
    int k = kc16*16 + (lane & 3)*2;
    __half2 h0 = __halves2half2(wall_h(w3,w4,w5, na, k),     wall_h(w3,w4,w5, na, k + 1));
    __half2 h1 = __halves2half2(wall_h(w3,w4,w5, na, k + 8), wall_h(w3,w4,w5, na, k + 9));
    __half2 h2 = __halves2half2(wall_h(w3,w4,w5, nb, k),     wall_h(w3,w4,w5, nb, k + 1));
    __half2 h3 = __halves2half2(wall_h(w3,w4,w5, nb, k + 8), wall_h(w3,w4,w5, nb, k + 9));
    uint4 v = make_uint4(*(uint32_t*)&h0, *(uint32_t*)&h1, *(uint32_t*)&h2, *(uint32_t*)&h3);
    reinterpret_cast<uint4*>(g_Bh)[d4] = v;
}

__global__ void transpose_tw(const float* __restrict__ tw) {
    int idx = blockIdx.x * blockDim.x + threadIdx.x;
    if (idx >= FCAT*DOUT) return;
    int j = idx / DOUT, d = idx % DOUT;
    g_twT[idx] = tw[d*FCAT + j];
}

// ---------------- fp16 mma GEMM: Z = Ah @ Bh^T (fp16 out) ----------------
// CTA 128(M) x 256(N), 256 thr = 8 warps (2 x 4), warp tile 64x64.
// K = 10 chunks of 32 (2 x k16). 3-stage cp.async, one sync per chunk.
// smem: A stages 3 x 8192 at [0,24576); B stages 3 x 16384 at [24576,73728)
#define GEMM_SMEM 73728

__global__ void __launch_bounds__(256, 1) conv_gemm_mma() {
    extern __shared__ char smc[];
    const int tid  = threadIdx.x;
    const int lane = tid & 31, wid = tid >> 5;
    const int warp_m = wid & 1;          // 0..1 -> M offset warp_m*64
    const int warp_n = wid >> 1;         // 0..3 -> N offset warp_n*64
    const int by = blockIdx.y, bx = blockIdx.x;
    const int m0 = by * 128, n0 = bx * 256;

    const uint32_t smb = smem_u32(smc);
    const uint4* Ah4 = reinterpret_cast<const uint4*>(g_Ah);
    const uint4* Bh4 = reinterpret_cast<const uint4*>(g_Bh);

    float acc[4][8][4];
    #pragma unroll
    for (int mt = 0; mt < 4; mt++)
        #pragma unroll
        for (int nt = 0; nt < 8; nt++)
            #pragma unroll
            for (int i = 0; i < 4; i++) acc[mt][nt][i] = 0.f;

    // prologue: stage chunks 0,1  (chunk: A 512 u4, B 1024 u4)
    #pragma unroll
    for (int c = 0; c < 2; c++) {
        size_t aG = ((size_t)by*20 + c*2) * 256;
        size_t bG = ((size_t)bx*20 + c*2) * 512;
        #pragma unroll
        for (int i = 0; i < 2; i++)
            CP_ASYNC16(smb + c*8192 + (tid + i*256)*16, Ah4 + aG + tid + i*256);
        #pragma unroll
        for (int i = 0; i < 4; i++)
            CP_ASYNC16(smb + 24576 + c*16384 + (tid + i*256)*16, Bh4 + bG + tid + i*256);
        CP_COMMIT();
    }

    for (int c = 0; c < 10; c++) {
        const int buf = c % 3;
        if (c < 9) CP_WAIT(1); else CP_WAIT(0);
        __syncthreads();
        if (c + 2 < 10) {
            const int nb = (c + 2) % 3;
            size_t aG = ((size_t)by*20 + (c + 2)*2) * 256;
            size_t bG = ((size_t)bx*20 + (c + 2)*2) * 512;
            #pragma unroll
            for (int i = 0; i < 2; i++)
                CP_ASYNC16(smb + nb*8192 + (tid + i*256)*16, Ah4 + aG + tid + i*256);
            #pragma unroll
            for (int i = 0; i < 4; i++)
                CP_ASYNC16(smb + 24576 + nb*16384 + (tid + i*256)*16, Bh4 + bG + tid + i*256);
            CP_COMMIT();
        }

        const uint4* A4 = reinterpret_cast<const uint4*>(smc + buf*8192);
        const uint4* B4 = reinterpret_cast<const uint4*>(smc + 24576 + buf*16384);
        #pragma unroll
        for (int ks = 0; ks < 2; ks++) {
            uint32_t a[4][4], b[8][2];
            #pragma unroll
            for (int mt = 0; mt < 4; mt++) {
                uint4 v = A4[(ks*8 + warp_m*4 + mt)*32 + lane];
                a[mt][0] = v.x; a[mt][1] = v.y; a[mt][2] = v.z; a[mt][3] = v.w;
            }
            #pragma unroll
            for (int np = 0; np < 4; np++) {
                uint4 u = B4[(ks*16 + warp_n*4 + np)*32 + lane];
                b[2*np  ][0] = u.x; b[2*np  ][1] = u.y;
                b[2*np+1][0] = u.z; b[2*np+1][1] = u.w;
            }
            #pragma unroll
            for (int mt = 0; mt < 4; mt++)
                #pragma unroll
                for (int nt = 0; nt < 8; nt++)
                    mma_fp16(acc[mt][nt], a[mt], b[nt]);
        }
    }

    // epilogue -> fp16
    __half2* Z2 = reinterpret_cast<__half2*>(g_Zh);
    #pragma unroll
    for (int mt = 0; mt < 4; mt++) {
        int r = m0 + warp_m*64 + mt*16 + (lane >> 2);
        #pragma unroll
        for (int nt = 0; nt < 8; nt++) {
            int cc = n0 + warp_n*64 + nt*8 + (lane & 3)*2;
            Z2[((size_t) r      *NCOL + cc) >> 1] = __floats2half2_rn(acc[mt][nt][0], acc[mt][nt][1]);
            Z2[((size_t)(r + 8)*NCOL + cc) >> 1] = __floats2half2_rn(acc[mt][nt][2], acc[mt][nt][3]);
        }
    }
}

// ---------------- fused pool + relu + tanh projection ----------------
// smem-staged: stage all 50 token rows (768 fp16) coalesced, pool from smem.
// dyn smem: Zs[50*768 halves]=76800B | toks[50]=200B | pmax[384]=1536B | fsh[192]=768B
#define POOL_SMEM (76800 + 200 + 1536 + 768)
__global__ void __launch_bounds__(384) poolsutt_kernel(
        const int* __restrict__ sents,
        const float* __restrict__ b3, const float* __restrict__ b4,
        const float* __restrict__ b5, const float* __restrict__ tb) {
    extern __shared__ char psm[];
    __half* Zs   = reinterpret_cast<__half*>(psm);            // [50][768]
    int*    toks = reinterpret_cast<int*>(psm + 76800);       // [50]
    float*  pmax = reinterpret_cast<float*>(psm + 77000);     // [384]
    float*  fsh  = reinterpret_cast<float*>(psm + 78536);     // [192]
    const int n = blockIdx.x;
    const int tid = threadIdx.x;

    if (tid < SL) toks[tid] = sents[n*SL + tid];
    __syncthreads();

    // stage: 50 rows x 96 uint4 = 4800 uint4, coalesced
    {
        uint4* Zs4 = reinterpret_cast<uint4*>(Zs);
        const uint4* Zg4 = reinterpret_cast<const uint4*>(g_Zh);
        for (int i = tid; i < SL*96; i += 384) {
            int row = i / 96, c4 = i - row*96;
            Zs4[i] = Zg4[(size_t)toks[row]*96 + c4];
        }
    }
    __syncthreads();

    // pool from smem (2-way t-split)
    {
        const int half = tid / FCAT;
        const int f = tid - half*FCAT;
        const int fi = f >> 6, o = f & 63;
        const int fs  = 3 + fi;
        const int off = (fi == 0) ? 0 : (fi == 1) ? 192 : 448;
        const int T = SL - fs + 1;
        const int t0 = half ? (T >> 1) : 0;
        const int t1 = half ? T : (T >> 1);
        float mx = -1e30f;
        for (int t = t0; t < t1; t++) {
            float v = 0.f;
            #pragma unroll 5
            for (int dt = 0; dt < fs; dt++)
                v += __half2float(Zs[(t + dt)*NCOL + off + dt*64 + o]);
            mx = fmaxf(mx, v);
        }
        pmax[tid] = mx;
    }
    __syncthreads();
    if (tid < FCAT) {
        int fi = tid >> 6, o = tid & 63;
        float bias = (fi == 0) ? b3[o] : (fi == 1) ? b4[o] : b5[o];
        float mx = fmaxf(pmax[tid], pmax[tid + FCAT]);
        fsh[tid] = fmaxf(0.f, mx + bias);
    }
    __syncthreads();
    if (tid < DOUT) {
        float acc = tb[tid];
        #pragma unroll 8
        for (int j = 0; j < FCAT; j++) acc += fsh[j] * g_twT[j*DOUT + tid];
        g_sutt[n*DOUT + tid] = tanhf(acc);
    }
}

// ---------------- GRU input projection ----------------
__global__ void __launch_bounds__(256) xproj_kernel(
        const float* __restrict__ wih, const float* __restrict__ bih) {
    __shared__ float ss[16][DOUT];
    const int tid = threadIdx.x;
    const int v0 = blockIdx.x * 16;
    for (int idx = tid; idx < 16*DOUT; idx += 256) {
        int r = idx / DOUT, d = idx % DOUT;
        int v = v0 + r;
        ss[r][d] = (v < NB) ? g_sutt[v*DOUT + d] : 0.f;
    }
    __syncthreads();
    for (int idx = tid; idx < 16*3*DOUT; idx += 256) {
        int j = idx >> 4, r = idx & 15;
        int v = v0 + r;
        if (v >= NB) continue;
        const float4* wI = reinterpret_cast<const float4*>(wih + j*DOUT);
        const float4* xv = reinterpret_cast<const float4*>(ss[r]);
        float acc = 0.f;
        #pragma unroll
        for (int k = 0; k < DOUT/4; k++) {
            float4 w = wI[k], x = xv[k];
            acc += w.x*x.x + w.y*x.y + w.z*x.z + w.w*x.w;
        }
        g_xproj[v*3*DOUT + j] = acc + bih[j];
    }
}

// ---------------- fused GRU: all 10 steps, whh resident in smem ----------------
#define GRU_SMEM ((30000 + 300 + 300 + 1600 + 4800) * 4)
__global__ void __launch_bounds__(256) gru_fused(
        const float* __restrict__ whh, const float* __restrict__ bhh,
        const float* __restrict__ bih) {
    extern __shared__ float smg[];
    float* whh_s = smg;
    float* bhh_s = smg + 30000;
    float* bih_s = bhh_s + 300;
    float* hs    = bih_s + 300;        // [16][100]
    float* gh    = hs + 1600;          // [16][300]
    const int tid = threadIdx.x;
    const int b0 = blockIdx.x * 16;

    for (int i = tid; i < 30000; i += 256) whh_s[i] = whh[i];
    for (int i = tid; i < 300; i += 256) { bhh_s[i] = bhh[i]; bih_s[i] = bih[i]; }
    for (int i = tid; i < 1600; i += 256) hs[i] = 0.f;
    __syncthreads();

    for (int s = 0; s < WIND; s++) {
        for (int idx = tid; idx < 16*3*DOUT; idx += 256) {
            int j = idx >> 4, r = idx & 15;
            const float4* wH = reinterpret_cast<const float4*>(whh_s + j*DOUT);
            const float4* hv = reinterpret_cast<const float4*>(hs + r*DOUT);
            float acc = 0.f;
            #pragma unroll
            for (int k = 0; k < DOUT/4; k++) {
                float4 w = wH[k], h = hv[k];
                acc += w.x*h.x + w.y*h.y + w.z*h.z + w.w*h.w;
            }
            gh[r*3*DOUT + j] = acc + bhh_s[j];
        }
        __syncthreads();
        for (int idx = tid; idx < 16*DOUT; idx += 256) {
            int r = idx / DOUT, d = idx % DOUT;
            int b = b0 + r;
            if (b >= NB) continue;
            int src = b + s - (WIND - 1);
            float giR, giZ, giN, xv;
            if (src >= 0) {
                const float* xp = g_xproj + src*3*DOUT;
                giR = xp[d]; giZ = xp[DOUT + d]; giN = xp[2*DOUT + d];
                xv = g_sutt[src*DOUT + d];
            } else {
                giR = bih_s[d]; giZ = bih_s[DOUT + d]; giN = bih_s[2*DOUT + d];
                xv = 0.f;
            }
            float hr = gh[r*3*DOUT + d], hz = gh[r*3*DOUT + DOUT + d], hn = gh[r*3*DOUT + 2*DOUT + d];
            float rr = 1.f / (1.f + expf(-(giR + hr)));
            float zz = 1.f / (1.f + expf(-(giZ + hz)));
            float nn = tanhf(giN + rr*hn);
            float hnew = (1.f - zz)*nn + zz*hs[r*DOUT + d];
            hs[r*DOUT + d] = hnew;
            g_memb[(b*WIND + s)*DOUT + d] = xv + hnew;
        }
        __syncthreads();
    }
}

// ---------------- 3-hop attention ----------------
__global__ void attn_kernel(float* __restrict__ attn_out) {
    __shared__ float M[WIND][DOUT];
    __shared__ float q[DOUT];
    __shared__ float l[WIND];
    __shared__ float a[WIND];
    const int b = blockIdx.x;
    const int tid = threadIdx.x;

    for (int idx = tid; idx < WIND*DOUT; idx += blockDim.x)
        M[idx/DOUT][idx%DOUT] = g_memb[(b*WIND)*DOUT + idx];
    if (tid < DOUT) q[tid] = g_sutt[(b+1)*DOUT + tid];
    __syncthreads();

    for (int hop = 0; hop < HOPS; hop++) {
        if (tid < WIND) {
            float acc = 0.f;
            #pragma unroll 4
            for (int d = 0; d < DOUT; d++) acc += q[d] * M[tid][d];
            bool valid = (b + tid - (WIND - 1)) >= 0;
            l[tid] = valid ? acc : -1e10f;
        }
        __syncthreads();
        if (tid == 0) {
            float mx = -1e30f;
            for (int k = 0; k < WIND; k++) mx = fmaxf(mx, l[k]);
            float sum = 0.f;
            for (int k = 0; k < WIND; k++) { a[k] = expf(l[k] - mx); sum += a[k]; }
            float inv = 1.f / sum;
            for (int k = 0; k < WIND; k++) a[k] *= inv;
        }
        __syncthreads();
        if (tid < WIND)
            attn_out[hop*(NB*WIND) + b*WIND + tid] = a[tid];
        if (tid < DOUT) {
            float acc = 0.f;
            #pragma unroll
            for (int k = 0; k < WIND; k++) acc += a[k] * M[k][tid];
            q[tid] += acc;
        }
        __syncthreads();
    }
    if (tid < DOUT) g_q[b*DOUT + tid] = q[tid];
}

// ---------------- classifier + log_softmax ----------------
__global__ void cls_kernel(const float* __restrict__ cw,
                           const float* __restrict__ cb,
                           float* __restrict__ pred_out) {
    int row = blockIdx.x * blockDim.x + threadIdx.x;
    if (row >= NU) return;
    const float* s = (row == 0) ? g_sutt : (g_q + (row - 1)*DOUT);
    float lg[NC];
    #pragma unroll
    for (int c = 0; c < NC; c++) {
        float acc = cb[c];
        const float* wr = cw + c*DOUT;
        #pragma unroll 4
        for (int k = 0; k < DOUT; k++) acc += s[k] * wr[k];
        lg[c] = acc;
    }
    float mx = lg[0];
    #pragma unroll
    for (int c = 1; c < NC; c++) mx = fmaxf(mx, lg[c]);
    float sum = 0.f;
    #pragma unroll
    for (int c = 0; c < NC; c++) sum += expf(lg[c] - mx);
    float lse = mx + logf(sum);
    #pragma unroll
    for (int c = 0; c < NC; c++) pred_out[row*NC + c] = lg[c] - lse;
}

// ---------------- launch sequence ----------------
extern "C" void kernel_launch(void* const* d_in, const int* in_sizes, int n_in,
                              void* d_out, int out_size) {
    const int*   sents   = (const int*)  d_in[0];
    const float* emb     = (const float*)d_in[2];
    const float* trans_w = (const float*)d_in[3];
    const float* trans_b = (const float*)d_in[4];
    const float* gru_wih = (const float*)d_in[5];
    const float* gru_whh = (const float*)d_in[6];
    const float* gru_bih = (const float*)d_in[7];
    const float* gru_bhh = (const float*)d_in[8];
    const float* cls_w   = (const float*)d_in[9];
    const float* cls_b   = (const float*)d_in[10];
    const float* conv_w3 = (const float*)d_in[11];
    const float* conv_b3 = (const float*)d_in[12];
    const float* conv_w4 = (const float*)d_in[13];
    const float* conv_b4 = (const float*)d_in[14];
    const float* conv_w5 = (const float*)d_in[15];
    const float* conv_b5 = (const float*)d_in[16];

    float* outF = (float*)d_out;
    float* pred_out = outF;
    float* attn_out;
    if (out_size >= NU*NC + HOPS*NB*WIND) attn_out = outF + NU*NC;
    else cudaGetSymbolAddress((void**)&attn_out, g_attn_scratch);

    cudaFuncSetAttribute(conv_gemm_mma,   cudaFuncAttributeMaxDynamicSharedMemorySize, GEMM_SMEM);
    cudaFuncSetAttribute(poolsutt_kernel, cudaFuncAttributeMaxDynamicSharedMemorySize, POOL_SMEM);
    cudaFuncSetAttribute(gru_fused,       cudaFuncAttributeMaxDynamicSharedMemorySize, GRU_SMEM);

    pack_Ah<<<(int)(((size_t)VPAD*KPAD/8 + 255)/256), 256>>>(emb);
    pack_Bh<<<(NCOL*KPAD/8 + 255)/256, 256>>>(conv_w3, conv_w4, conv_w5);
    transpose_tw<<<(FCAT*DOUT + 255)/256, 256>>>(trans_w);

    dim3 ggrid(NCOL/256, VPAD/128);   // (3, 391)
    conv_gemm_mma<<<ggrid, 256, GEMM_SMEM>>>();

    poolsutt_kernel<<<NU, 384, POOL_SMEM>>>(sents, conv_b3, conv_b4, conv_b5, trans_b);
    xproj_kernel<<<(NB + 15)/16, 256>>>(gru_wih, gru_bih);
    gru_fused<<<(NB + 15)/16, 256, GRU_SMEM>>>(gru_whh, gru_bhh, gru_bih);

    attn_kernel<<<NB, 128>>>(attn_out);
    cls_kernel<<<(NU + 255)/256, 256>>>(cls_w, cls_b, pred_out);
}

// round 9
// speedup vs baseline: 6.2765x; 1.0582x over previous
#include <cuda_runtime.h>
#include <cuda_fp16.h>
#include <math.h>
#include <stdint.h>

// ---------------- problem constants ----------------
#define NU    2048
#define SL    50
#define DE    300
#define KPAD  320      // 20 k-groups of 16; 10 chunks of 32
#define DOUT  100
#define NC    7
#define WIND  10
#define HOPS  3
#define NB    2047
#define VOCAB 50000
#define VPAD  50048    // 391 * 128
#define NCOL  768
#define FCAT  192

// ---------------- static scratch ----------------
__device__ __half g_Ah[(size_t)VPAD*KPAD];      // A fp16 fragment order (128-row mblk)
__device__ __half g_Bh[NCOL*KPAD];              // B fp16 nt-pair fragment order (128-col nblk)
__device__ __half g_Zh[(size_t)VPAD*NCOL];      // fp16 projections (77 MB)
__device__ float g_twT[FCAT*DOUT];
__device__ float g_sutt[NU*DOUT];
__device__ float g_xproj[NB*3*DOUT];
__device__ float g_memb[NB*WIND*DOUT];
__device__ float g_q[NB*DOUT];
__device__ float g_attn_scratch[HOPS*NB*WIND];

// ---------------- helpers ----------------
__device__ __forceinline__ uint32_t smem_u32(const void* p) {
    uint32_t a;
    asm("{ .reg .u64 t; cvta.to.shared.u64 t, %1; cvt.u32.u64 %0, t; }" : "=r"(a) : "l"(p));
    return a;
}
#define CP_ASYNC16(sa, gp) asm volatile("cp.async.cg.shared.global [%0], [%1], 16;" :: "r"(sa), "l"(gp) : "memory")
#define CP_COMMIT()        asm volatile("cp.async.commit_group;" ::: "memory")
#define CP_WAIT(n)         asm volatile("cp.async.wait_group %0;" :: "n"(n) : "memory")

__device__ __forceinline__ void mma_fp16(float* d, const uint32_t* a, const uint32_t* b) {
    asm volatile("mma.sync.aligned.m16n8k16.row.col.f32.f16.f16.f32 "
        "{%0,%1,%2,%3}, {%4,%5,%6,%7}, {%8,%9}, {%0,%1,%2,%3};"
        : "+f"(d[0]), "+f"(d[1]), "+f"(d[2]), "+f"(d[3])
        : "r"(a[0]), "r"(a[1]), "r"(a[2]), "r"(a[3]), "r"(b[0]), "r"(b[1]));
}

// ---------------- pack A (dst-linear, fp16 fragment order) ----------------
__device__ __forceinline__ __half emb_h(const float* emb, int m, int k) {
    if (m >= VOCAB || k >= DE) return __float2half_rn(0.f);
    return __float2half_rn(emb[(size_t)m*DE + k]);
}
__global__ void pack_Ah(const float* __restrict__ emb) {
    size_t d4 = (size_t)blockIdx.x * blockDim.x + threadIdx.x;
    if (d4 >= (size_t)VPAD*KPAD/8) return;
    int lane = (int)(d4 & 31);
    int r16  = (int)((d4 >> 5) & 7);
    size_t rest = d4 >> 8;
    int kc16 = (int)(rest % 20);
    int mblk = (int)(rest / 20);
    int m = mblk*128 + r16*16 + (lane >> 2);
    int k = kc16*16 + (lane & 3)*2;
    __half2 h0 = __halves2half2(emb_h(emb, m,     k),     emb_h(emb, m,     k + 1));
    __half2 h1 = __halves2half2(emb_h(emb, m + 8, k),     emb_h(emb, m + 8, k + 1));
    __half2 h2 = __halves2half2(emb_h(emb, m,     k + 8), emb_h(emb, m,     k + 9));
    __half2 h3 = __halves2half2(emb_h(emb, m + 8, k + 8), emb_h(emb, m + 8, k + 9));
    uint4 v = make_uint4(*(uint32_t*)&h0, *(uint32_t*)&h1, *(uint32_t*)&h2, *(uint32_t*)&h3);
    reinterpret_cast<uint4*>(g_Ah)[d4] = v;
}

// ---------------- pack B (dst-linear, 128-col nblk, nt-pair order) ----------
__device__ __forceinline__ __half wall_h(const float* w3, const float* w4,
                                         const float* w5, int c, int k) {
    if (k >= DE) return __float2half_rn(0.f);
    float v;
    if (c < 192)      { int cc = c;       int dt = cc >> 6, o = cc & 63; v = w3[(o*3 + dt)*DE + k]; }
    else if (c < 448) { int cc = c - 192; int dt = cc >> 6, o = cc & 63; v = w4[(o*4 + dt)*DE + k]; }
    else              { int cc = c - 448; int dt = cc >> 6, o = cc & 63; v = w5[(o*5 + dt)*DE + k]; }
    return __float2half_rn(v);
}
__global__ void pack_Bh(const float* __restrict__ w3,
                        const float* __restrict__ w4,
                        const float* __restrict__ w5) {
    int d4 = blockIdx.x * blockDim.x + threadIdx.x;
    if (d4 >= NCOL*KPAD/8) return;
    int lane = d4 & 31;
    int np   = (d4 >> 5) & 7;       // 8 nt-pairs per kc16 (128 cols)
    int rest = d4 >> 8;
    int kc16 = rest % 20;
    int nblk = rest / 20;
    int na = nblk*128 + np*16 + (lane >> 2);
    int nb = na + 8;
    int k = kc16*16 + (lane & 3)*2;
    __half2 h0 = __halves2half2(wall_h(w3,w4,w5, na, k),     wall_h(w3,w4,w5, na, k + 1));
    __half2 h1 = __halves2half2(wall_h(w3,w4,w5, na, k + 8), wall_h(w3,w4,w5, na, k + 9));
    __half2 h2 = __halves2half2(wall_h(w3,w4,w5, nb, k),     wall_h(w3,w4,w5, nb, k + 1));
    __half2 h3 = __halves2half2(wall_h(w3,w4,w5, nb, k + 8), wall_h(w3,w4,w5, nb, k + 9));
    uint4 v = make_uint4(*(uint32_t*)&h0, *(uint32_t*)&h1, *(uint32_t*)&h2, *(uint32_t*)&h3);
    reinterpret_cast<uint4*>(g_Bh)[d4] = v;
}

__global__ void transpose_tw(const float* __restrict__ tw) {
    int idx = blockIdx.x * blockDim.x + threadIdx.x;
    if (idx >= FCAT*DOUT) return;
    int j = idx / DOUT, d = idx % DOUT;
    g_twT[idx] = tw[d*FCAT + j];
}

// ---------------- fp16 mma GEMM: Z = Ah @ Bh^T (fp16 out) ----------------
// CTA 128(M) x 128(N), 256 thr = 8 warps (4 M x 2 N), warp tile 32x64.
// 2 CTAs/SM (launch_bounds cap 128 regs). 3-stage cp.async, one sync per chunk.
// smem: A stages 3 x 8192 at [0,24576); B stages 3 x 8192 at [24576,49152)
#define GEMM_SMEM 49152

__global__ void __launch_bounds__(256, 2) conv_gemm_mma() {
    extern __shared__ char smc[];
    const int tid  = threadIdx.x;
    const int lane = tid & 31, wid = tid >> 5;
    const int warp_m = wid & 3;          // M offset warp_m*32
    const int warp_n = wid >> 2;         // N offset warp_n*64
    const int by = blockIdx.y, bx = blockIdx.x;
    const int m0 = by * 128, n0 = bx * 128;

    const uint32_t smb = smem_u32(smc);
    const uint4* Ah4 = reinterpret_cast<const uint4*>(g_Ah);
    const uint4* Bh4 = reinterpret_cast<const uint4*>(g_Bh);

    float acc[2][8][4];
    #pragma unroll
    for (int mt = 0; mt < 2; mt++)
        #pragma unroll
        for (int nt = 0; nt < 8; nt++)
            #pragma unroll
            for (int i = 0; i < 4; i++) acc[mt][nt][i] = 0.f;

    // prologue: stage chunks 0,1  (chunk: A 512 u4, B 512 u4)
    #pragma unroll
    for (int c = 0; c < 2; c++) {
        size_t aG = ((size_t)by*20 + c*2) * 256;
        size_t bG = ((size_t)bx*20 + c*2) * 256;
        #pragma unroll
        for (int i = 0; i < 2; i++) {
            CP_ASYNC16(smb +         c*8192 + (tid + i*256)*16, Ah4 + aG + tid + i*256);
            CP_ASYNC16(smb + 24576 + c*8192 + (tid + i*256)*16, Bh4 + bG + tid + i*256);
        }
        CP_COMMIT();
    }

    for (int c = 0; c < 10; c++) {
        const int buf = c % 3;
        if (c < 9) CP_WAIT(1); else CP_WAIT(0);
        __syncthreads();
        if (c + 2 < 10) {
            const int nb = (c + 2) % 3;
            size_t aG = ((size_t)by*20 + (c + 2)*2) * 256;
            size_t bG = ((size_t)bx*20 + (c + 2)*2) * 256;
            #pragma unroll
            for (int i = 0; i < 2; i++) {
                CP_ASYNC16(smb +         nb*8192 + (tid + i*256)*16, Ah4 + aG + tid + i*256);
                CP_ASYNC16(smb + 24576 + nb*8192 + (tid + i*256)*16, Bh4 + bG + tid + i*256);
            }
            CP_COMMIT();
        }

        const uint4* A4 = reinterpret_cast<const uint4*>(smc + buf*8192);
        const uint4* B4 = reinterpret_cast<const uint4*>(smc + 24576 + buf*8192);
        #pragma unroll
        for (int ks = 0; ks < 2; ks++) {
            uint32_t a[2][4], b[8][2];
            #pragma unroll
            for (int mt = 0; mt < 2; mt++) {
                uint4 v = A4[(ks*8 + warp_m*2 + mt)*32 + lane];
                a[mt][0] = v.x; a[mt][1] = v.y; a[mt][2] = v.z; a[mt][3] = v.w;
            }
            #pragma unroll
            for (int np = 0; np < 4; np++) {
                uint4 u = B4[(ks*8 + warp_n*4 + np)*32 + lane];
                b[2*np  ][0] = u.x; b[2*np  ][1] = u.y;
                b[2*np+1][0] = u.z; b[2*np+1][1] = u.w;
            }
            #pragma unroll
            for (int mt = 0; mt < 2; mt++)
                #pragma unroll
                for (int nt = 0; nt < 8; nt++)
                    mma_fp16(acc[mt][nt], a[mt], b[nt]);
        }
    }

    // epilogue -> fp16
    __half2* Z2 = reinterpret_cast<__half2*>(g_Zh);
    #pragma unroll
    for (int mt = 0; mt < 2; mt++) {
        int r = m0 + warp_m*32 + mt*16 + (lane >> 2);
        #pragma unroll
        for (int nt = 0; nt < 8; nt++) {
            int cc = n0 + warp_n*64 + nt*8 + (lane & 3)*2;
            Z2[((size_t) r      *NCOL + cc) >> 1] = __floats2half2_rn(acc[mt][nt][0], acc[mt][nt][1]);
            Z2[((size_t)(r + 8)*NCOL + cc) >> 1] = __floats2half2_rn(acc[mt][nt][2], acc[mt][nt][3]);
        }
    }
}

// ---------------- fused pool + relu + tanh projection (smem staged) ---------
#define POOL_SMEM (76800 + 200 + 1536 + 768)
__global__ void __launch_bounds__(384) poolsutt_kernel(
        const int* __restrict__ sents,
        const float* __restrict__ b3, const float* __restrict__ b4,
        const float* __restrict__ b5, const float* __restrict__ tb) {
    extern __shared__ char psm[];
    __half* Zs   = reinterpret_cast<__half*>(psm);            // [50][768]
    int*    toks = reinterpret_cast<int*>(psm + 76800);       // [50]
    float*  pmax = reinterpret_cast<float*>(psm + 77000);     // [384]
    float*  fsh  = reinterpret_cast<float*>(psm + 78536);     // [192]
    const int n = blockIdx.x;
    const int tid = threadIdx.x;

    if (tid < SL) toks[tid] = sents[n*SL + tid];
    __syncthreads();
    {
        uint4* Zs4 = reinterpret_cast<uint4*>(Zs);
        const uint4* Zg4 = reinterpret_cast<const uint4*>(g_Zh);
        for (int i = tid; i < SL*96; i += 384) {
            int row = i / 96, c4 = i - row*96;
            Zs4[i] = Zg4[(size_t)toks[row]*96 + c4];
        }
    }
    __syncthreads();
    {
        const int half = tid / FCAT;
        const int f = tid - half*FCAT;
        const int fi = f >> 6, o = f & 63;
        const int fs  = 3 + fi;
        const int off = (fi == 0) ? 0 : (fi == 1) ? 192 : 448;
        const int T = SL - fs + 1;
        const int t0 = half ? (T >> 1) : 0;
        const int t1 = half ? T : (T >> 1);
        float mx = -1e30f;
        for (int t = t0; t < t1; t++) {
            float v = 0.f;
            #pragma unroll 5
            for (int dt = 0; dt < fs; dt++)
                v += __half2float(Zs[(t + dt)*NCOL + off + dt*64 + o]);
            mx = fmaxf(mx, v);
        }
        pmax[tid] = mx;
    }
    __syncthreads();
    if (tid < FCAT) {
        int fi = tid >> 6, o = tid & 63;
        float bias = (fi == 0) ? b3[o] : (fi == 1) ? b4[o] : b5[o];
        float mx = fmaxf(pmax[tid], pmax[tid + FCAT]);
        fsh[tid] = fmaxf(0.f, mx + bias);
    }
    __syncthreads();
    if (tid < DOUT) {
        float acc = tb[tid];
        #pragma unroll 8
        for (int j = 0; j < FCAT; j++) acc += fsh[j] * g_twT[j*DOUT + tid];
        g_sutt[n*DOUT + tid] = tanhf(acc);
    }
}

// ---------------- GRU input projection ----------------
__global__ void __launch_bounds__(256) xproj_kernel(
        const float* __restrict__ wih, const float* __restrict__ bih) {
    __shared__ float ss[16][DOUT];
    const int tid = threadIdx.x;
    const int v0 = blockIdx.x * 16;
    for (int idx = tid; idx < 16*DOUT; idx += 256) {
        int r = idx / DOUT, d = idx % DOUT;
        int v = v0 + r;
        ss[r][d] = (v < NB) ? g_sutt[v*DOUT + d] : 0.f;
    }
    __syncthreads();
    for (int idx = tid; idx < 16*3*DOUT; idx += 256) {
        int j = idx >> 4, r = idx & 15;
        int v = v0 + r;
        if (v >= NB) continue;
        const float4* wI = reinterpret_cast<const float4*>(wih + j*DOUT);
        const float4* xv = reinterpret_cast<const float4*>(ss[r]);
        float acc = 0.f;
        #pragma unroll
        for (int k = 0; k < DOUT/4; k++) {
            float4 w = wI[k], x = xv[k];
            acc += w.x*x.x + w.y*x.y + w.z*x.z + w.w*x.w;
        }
        g_xproj[v*3*DOUT + j] = acc + bih[j];
    }
}

// ---------------- fused GRU: weights-in-registers, broadcast-h ----------------
// 128 blocks x 16 rows, 320 thr. Thread j (0..299) owns whh row j in registers
// for ALL 10 steps; hs reads are warp-broadcast float4 LDS.
#define GRB 16
#define GRU_T 320
__global__ void __launch_bounds__(GRU_T) gru_fused(
        const float* __restrict__ whh, const float* __restrict__ bhh,
        const float* __restrict__ bih) {
    __shared__ float hs[GRB*DOUT];       // 16 x 100
    __shared__ float gh[GRB*3*DOUT];     // 16 x 300
    const int tid = threadIdx.x;
    const int b0 = blockIdx.x * GRB;
    const int j = tid;
    const bool active = (j < 3*DOUT);

    float w[DOUT];
    float bh = 0.f;
    if (active) {
        const float4* wr = reinterpret_cast<const float4*>(whh + j*DOUT);
        #pragma unroll
        for (int k4 = 0; k4 < DOUT/4; k4++) {
            float4 v = wr[k4];
            w[4*k4] = v.x; w[4*k4+1] = v.y; w[4*k4+2] = v.z; w[4*k4+3] = v.w;
        }
        bh = bhh[j];
    }
    for (int i = tid; i < GRB*DOUT; i += GRU_T) hs[i] = 0.f;
    __syncthreads();

    for (int s = 0; s < WIND; s++) {
        if (active) {
            #pragma unroll
            for (int r = 0; r < GRB; r++) {
                const float4* h4 = reinterpret_cast<const float4*>(hs + r*DOUT);
                float acc = 0.f;
                #pragma unroll
                for (int k4 = 0; k4 < DOUT/4; k4++) {
                    float4 h = h4[k4];
                    acc += w[4*k4]*h.x + w[4*k4+1]*h.y + w[4*k4+2]*h.z + w[4*k4+3]*h.w;
                }
                gh[r*3*DOUT + j] = acc + bh;
            }
        }
        __syncthreads();
        for (int idx = tid; idx < GRB*DOUT; idx += GRU_T) {
            int r = idx / DOUT, d = idx - r*DOUT;
            int b = b0 + r;
            if (b < NB) {
                int src = b + s - (WIND - 1);
                float giR, giZ, giN, xv;
                if (src >= 0) {
                    const float* xp = g_xproj + src*3*DOUT;
                    giR = xp[d]; giZ = xp[DOUT + d]; giN = xp[2*DOUT + d];
                    xv = g_sutt[src*DOUT + d];
                } else {
                    giR = bih[d]; giZ = bih[DOUT + d]; giN = bih[2*DOUT + d];
                    xv = 0.f;
                }
                float hr = gh[r*3*DOUT + d];
                float hz = gh[r*3*DOUT + DOUT + d];
                float hn = gh[r*3*DOUT + 2*DOUT + d];
                float rr = 1.f / (1.f + expf(-(giR + hr)));
                float zz = 1.f / (1.f + expf(-(giZ + hz)));
                float nn = tanhf(giN + rr*hn);
                float hnew = (1.f - zz)*nn + zz*hs[r*DOUT + d];
                hs[r*DOUT + d] = hnew;
                g_memb[(b*WIND + s)*DOUT + d] = xv + hnew;
            }
        }
        __syncthreads();
    }
}

// ---------------- 3-hop attention ----------------
__global__ void attn_kernel(float* __restrict__ attn_out) {
    __shared__ float M[WIND][DOUT];
    __shared__ float q[DOUT];
    __shared__ float l[WIND];
    __shared__ float a[WIND];
    const int b = blockIdx.x;
    const int tid = threadIdx.x;

    for (int idx = tid; idx < WIND*DOUT; idx += blockDim.x)
        M[idx/DOUT][idx%DOUT] = g_memb[(b*WIND)*DOUT + idx];
    if (tid < DOUT) q[tid] = g_sutt[(b+1)*DOUT + tid];
    __syncthreads();

    for (int hop = 0; hop < HOPS; hop++) {
        if (tid < WIND) {
            float acc = 0.f;
            #pragma unroll 4
            for (int d = 0; d < DOUT; d++) acc += q[d] * M[tid][d];
            bool valid = (b + tid - (WIND - 1)) >= 0;
            l[tid] = valid ? acc : -1e10f;
        }
        __syncthreads();
        if (tid == 0) {
            float mx = -1e30f;
            for (int k = 0; k < WIND; k++) mx = fmaxf(mx, l[k]);
            float sum = 0.f;
            for (int k = 0; k < WIND; k++) { a[k] = expf(l[k] - mx); sum += a[k]; }
            float inv = 1.f / sum;
            for (int k = 0; k < WIND; k++) a[k] *= inv;
        }
        __syncthreads();
        if (tid < WIND)
            attn_out[hop*(NB*WIND) + b*WIND + tid] = a[tid];
        if (tid < DOUT) {
            float acc = 0.f;
            #pragma unroll
            for (int k = 0; k < WIND; k++) acc += a[k] * M[k][tid];
            q[tid] += acc;
        }
        __syncthreads();
    }
    if (tid < DOUT) g_q[b*DOUT + tid] = q[tid];
}

// ---------------- classifier + log_softmax ----------------
__global__ void cls_kernel(const float* __restrict__ cw,
                           const float* __restrict__ cb,
                           float* __restrict__ pred_out) {
    int row = blockIdx.x * blockDim.x + threadIdx.x;
    if (row >= NU) return;
    const float* s = (row == 0) ? g_sutt : (g_q + (row - 1)*DOUT);
    float lg[NC];
    #pragma unroll
    for (int c = 0; c < NC; c++) {
        float acc = cb[c];
        const float* wr = cw + c*DOUT;
        #pragma unroll 4
        for (int k = 0; k < DOUT; k++) acc += s[k] * wr[k];
        lg[c] = acc;
    }
    float mx = lg[0];
    #pragma unroll
    for (int c = 1; c < NC; c++) mx = fmaxf(mx, lg[c]);
    float sum = 0.f;
    #pragma unroll
    for (int c = 0; c < NC; c++) sum += expf(lg[c] - mx);
    float lse = mx + logf(sum);
    #pragma unroll
    for (int c = 0; c < NC; c++) pred_out[row*NC + c] = lg[c] - lse;
}

// ---------------- launch sequence ----------------
extern "C" void kernel_launch(void* const* d_in, const int* in_sizes, int n_in,
                              void* d_out, int out_size) {
    const int*   sents   = (const int*)  d_in[0];
    const float* emb     = (const float*)d_in[2];
    const float* trans_w = (const float*)d_in[3];
    const float* trans_b = (const float*)d_in[4];
    const float* gru_wih = (const float*)d_in[5];
    const float* gru_whh = (const float*)d_in[6];
    const float* gru_bih = (const float*)d_in[7];
    const float* gru_bhh = (const float*)d_in[8];
    const float* cls_w   = (const float*)d_in[9];
    const float* cls_b   = (const float*)d_in[10];
    const float* conv_w3 = (const float*)d_in[11];
    const float* conv_b3 = (const float*)d_in[12];
    const float* conv_w4 = (const float*)d_in[13];
    const float* conv_b4 = (const float*)d_in[14];
    const float* conv_w5 = (const float*)d_in[15];
    const float* conv_b5 = (const float*)d_in[16];

    float* outF = (float*)d_out;
    float* pred_out = outF;
    float* attn_out;
    if (out_size >= NU*NC + HOPS*NB*WIND) attn_out = outF + NU*NC;
    else cudaGetSymbolAddress((void**)&attn_out, g_attn_scratch);

    cudaFuncSetAttribute(conv_gemm_mma,   cudaFuncAttributeMaxDynamicSharedMemorySize, GEMM_SMEM);
    cudaFuncSetAttribute(poolsutt_kernel, cudaFuncAttributeMaxDynamicSharedMemorySize, POOL_SMEM);

    pack_Ah<<<(int)(((size_t)VPAD*KPAD/8 + 255)/256), 256>>>(emb);
    pack_Bh<<<(NCOL*KPAD/8 + 255)/256, 256>>>(conv_w3, conv_w4, conv_w5);
    transpose_tw<<<(FCAT*DOUT + 255)/256, 256>>>(trans_w);

    dim3 ggrid(NCOL/128, VPAD/128);   // (6, 391)
    conv_gemm_mma<<<ggrid, 256, GEMM_SMEM>>>();

    poolsutt_kernel<<<NU, 384, POOL_SMEM>>>(sents, conv_b3, conv_b4, conv_b5, trans_b);
    xproj_kernel<<<(NB + 15)/16, 256>>>(gru_wih, gru_bih);
    gru_fused<<<(NB + GRB - 1)/GRB, GRU_T>>>(gru_whh, gru_bhh, gru_bih);

    attn_kernel<<<NB, 128>>>(attn_out);
    cls_kernel<<<(NU + 255)/256, 256>>>(cls_w, cls_b, pred_out);
}